// round 8
// baseline (speedup 1.0000x reference)
#include <cuda_runtime.h>
#include <cuda_fp16.h>
#include <cstdint>
#include <cstddef>

// ---------------------------------------------------------------------------
// GAU denoising model. Single-term fp16 HMMA (mma.sync) GEMMs, fp32 elsewhere.
// Round 8: BK 32->64 (half the per-stage barriers), merged wconv so the
// ncu-captured launch (index 3) is gemm0.
// B=16, L=256 tokens, PD=192, H=768, E=1536, K=128, NL=24, rows=4096.
// ---------------------------------------------------------------------------

#define NB      16
#define LTOK    256
#define HD      768
#define ED      1536
#define KDIM    128
#define UVQK    3328
#define ROWS    4096
#define NLAYERS 24
#define PDIM    192

// ----- scratch (device globals; allocation is forbidden) --------------------
__device__ float g_h   [(size_t)ROWS * HD];
__device__ float g_xn  [(size_t)ROWS * HD];
__device__ __half g_xnh[(size_t)ROWS * HD];
__device__ float g_uvqk[(size_t)ROWS * UVQK];
__device__ __half g_attnh[(size_t)ROWS * LTOK];
__device__ __half g_vth[(size_t)NB * ED * LTOK];   // silu(v)^T per batch [E][L]
__device__ __half g_oh [(size_t)ROWS * ED];        // silu(u)*av
__device__ __half g_wuvh[(size_t)NLAYERS * UVQK * HD];   // Wuv^T [N][K]
__device__ __half g_woh [(size_t)NLAYERS * HD * ED];     // Wout^T [N][K]

// ---------------------------------------------------------------------------
// PTX helpers (sm_80-era; compile for base sm_100)
// ---------------------------------------------------------------------------
__device__ __forceinline__ uint32_t smem_u32(const void* p) {
    uint32_t a;
    asm("{ .reg .u64 t; cvta.to.shared.u64 t, %1; cvt.u32.u64 %0, t; }"
        : "=r"(a) : "l"(p));
    return a;
}
__device__ __forceinline__ void cp16(uint32_t dst, const void* src) {
    asm volatile("cp.async.cg.shared.global [%0], [%1], 16;"
                 :: "r"(dst), "l"(src) : "memory");
}
#define CP_COMMIT() asm volatile("cp.async.commit_group;" ::: "memory")
#define CP_WAIT(N)  asm volatile("cp.async.wait_group %0;" :: "n"(N) : "memory")

__device__ __forceinline__ void ldsm4(uint32_t* r, uint32_t addr) {
    asm volatile("ldmatrix.sync.aligned.m8n8.x4.shared.b16 {%0,%1,%2,%3}, [%4];"
                 : "=r"(r[0]), "=r"(r[1]), "=r"(r[2]), "=r"(r[3]) : "r"(addr));
}
__device__ __forceinline__ void mma16816(float* c, const uint32_t* a,
                                         uint32_t b0, uint32_t b1) {
    asm volatile(
        "mma.sync.aligned.m16n8k16.row.col.f32.f16.f16.f32 "
        "{%0,%1,%2,%3}, {%4,%5,%6,%7}, {%8,%9}, {%0,%1,%2,%3};"
        : "+f"(c[0]), "+f"(c[1]), "+f"(c[2]), "+f"(c[3])
        : "r"(a[0]), "r"(a[1]), "r"(a[2]), "r"(a[3]), "r"(b0), "r"(b1));
}

// ---------------------------------------------------------------------------
// fp16 GEMM via mma.sync. C[M,N] from A[M,K] (row-major) and B[N,K] (K-major).
// CTA tile 128x128, BK=64, 8 warps (2m x 4n), warp tile 64x32.
// Smem tile: 128 rows x 64 halves (128B/row), 8-way XOR swizzle on 16B chunks:
//   phys(r, c) = r*128 + ((c ^ (r&7)) << 4)          (c = k-chunk 0..7)
// k-step ks (16 halves) flips chunk bits: off(ks) = off(0) ^ (ks << 5).
// 3-stage cp.async pipeline (2 stages in flight behind compute).
// EPI 0: C = D        EPI 1: O = silu(U)*D -> fp16      EPI 2: C += D
// ---------------------------------------------------------------------------
#define TILE_B   16384                   // 128 rows x 128 B
#define O_A      0
#define O_B      (TILE_B)
#define STAGE_B  (2 * TILE_B)            // 32768 B
#define NSTAGE   3
#define GSMEM_SZ (NSTAGE * STAGE_B)      // 98304 B

__device__ __forceinline__ uint32_t swz64(uint32_t r, uint32_t c) {
    return r * 128u + ((c ^ (r & 7u)) << 4);
}

template <int EPI>
__global__ void __launch_bounds__(256, 2) mma_gemm(
    const __half* __restrict__ A, const __half* __restrict__ B,
    float* __restrict__ C, const float* __restrict__ U,
    __half* __restrict__ Oh,
    int K, int lda, int ldb, int ldc, int ldu, int ldo,
    long sA, long sB, long sC, long sU, long sO) {

    extern __shared__ char smem[];
    uint32_t sb = smem_u32(smem);
    int t = threadIdx.x, lane = t & 31, wid = t >> 5;
    int wm = (wid >> 2) * 64, wn = (wid & 3) * 32;
    int bn0 = blockIdx.x * 128, bm0 = blockIdx.y * 128;
    long z = blockIdx.z;
    A += z * sA; B += z * sB;
    if (EPI != 1) C += z * sC;
    if (EPI == 1) { U += z * sU; Oh += z * sO; }

    float acc[4][4][4] = {};            // [mtile][ntile][c0..c3]

    // Per-thread loader offsets: 1024 16B-chunks per tile, 4 per thread.
    uint32_t ld_row[4], ld_c[4], ld_d[4];
    #pragma unroll
    for (int i = 0; i < 4; i++) {
        int id = t + i * 256;
        ld_row[i] = (uint32_t)(id >> 3);
        ld_c[i]   = (uint32_t)(id & 7);
        ld_d[i]   = swz64(ld_row[i], ld_c[i]);
    }

    auto load_stage = [&](int buf, int kt) {
        uint32_t base = sb + buf * STAGE_B;
        #pragma unroll
        for (int i = 0; i < 4; i++)
            cp16(base + O_A + ld_d[i],
                 A + (size_t)(bm0 + ld_row[i]) * lda + kt + ld_c[i] * 8);
        #pragma unroll
        for (int i = 0; i < 4; i++)
            cp16(base + O_B + ld_d[i],
                 B + (size_t)(bn0 + ld_row[i]) * ldb + kt + ld_c[i] * 8);
        CP_COMMIT();
    };

    // ldsm offsets for k-step 0; k-step ks is offset ^ (ks<<5).
    uint32_t aoff[4], boff[2];
    {
        uint32_t ac = (uint32_t)(lane >> 4);                // A k-chunk (0..1)
        uint32_t ar = (uint32_t)(wm + (lane & 15));
        #pragma unroll
        for (int mt = 0; mt < 4; mt++) aoff[mt] = swz64(ar + mt * 16, ac);
        uint32_t bc = (uint32_t)((lane >> 3) & 1);          // B k-chunk (0..1)
        uint32_t br = (uint32_t)(wn + ((lane >> 4) << 3) + (lane & 7));
        #pragma unroll
        for (int ntp = 0; ntp < 2; ntp++) boff[ntp] = swz64(br + ntp * 16, bc);
    }

    int nk = K / 64;
    load_stage(0, 0);
    load_stage(1, 64);

    for (int s = 0; s < nk; s++) {
        CP_WAIT(1);                      // stage s resident; s+1 in flight
        __syncthreads();                 // everyone done reading stage s-1
        if (s + 2 < nk) load_stage((s + 2) % NSTAGE, (s + 2) * 64);
        else            CP_COMMIT();     // keep group accounting for the tail

        uint32_t base = sb + (s % NSTAGE) * STAGE_B;
        #pragma unroll
        for (int ks = 0; ks < 4; ks++) {
            uint32_t kx = (uint32_t)ks << 5;
            uint32_t bf[8];
            #pragma unroll
            for (int ntp = 0; ntp < 2; ntp++)
                ldsm4(bf + ntp * 4, base + O_B + (boff[ntp] ^ kx));
            #pragma unroll
            for (int mt = 0; mt < 4; mt++) {
                uint32_t af[4];
                ldsm4(af, base + O_A + (aoff[mt] ^ kx));
                #pragma unroll
                for (int nt = 0; nt < 4; nt++)
                    mma16816(acc[mt][nt], af, bf[nt * 2], bf[nt * 2 + 1]);
            }
        }
    }

    // -------- epilogue: direct fragment stores (32B sector per segment) -----
    int g = lane >> 2, tc = lane & 3;
    #pragma unroll
    for (int mt = 0; mt < 4; mt++) {
        #pragma unroll
        for (int nt = 0; nt < 4; nt++) {
            float* c = acc[mt][nt];
            int r0 = bm0 + wm + mt * 16 + g;
            int c0 = bn0 + wn + nt * 8 + tc * 2;
            #pragma unroll
            for (int half = 0; half < 2; half++) {
                int r = r0 + half * 8;
                float v0 = c[half * 2], v1 = c[half * 2 + 1];
                if (EPI == 0) {
                    float2 st = {v0, v1};
                    *(float2*)&C[(size_t)r * ldc + c0] = st;
                } else if (EPI == 1) {
                    const float* up = &U[(size_t)r * ldu + c0];
                    float u0 = up[0], u1 = up[1];
                    float o0 = (u0 / (1.f + expf(-u0))) * v0;
                    float o1 = (u1 / (1.f + expf(-u1))) * v1;
                    __half2 hp;
                    hp.x = __float2half(o0);
                    hp.y = __float2half(o1);
                    *(__half2*)&Oh[(size_t)r * ldo + c0] = hp;
                } else {
                    float2* p = (float2*)&C[(size_t)r * ldc + c0];
                    float2 old = *p;
                    old.x += v0; old.y += v1;
                    *p = old;
                }
            }
        }
    }
}

// ---------------------------------------------------------------------------
// Merged weight transpose + fp16 convert (ONE launch so gemm0 is launch #3).
// Wuv [768,3328] -> wuvh [3328,768]; Wout [1536,768] -> woh [768,1536].
// 1D grid over all 32x32 tiles of both tensors x 24 layers.
// ---------------------------------------------------------------------------
#define NT1 ((UVQK / 32) * (HD / 32))     // 104*24 = 2496 tiles/layer (Wuv)
#define NT2 ((HD / 32) * (ED / 32))       // 24*48  = 1152 tiles/layer (Wout)
#define WCONV_GRID (NLAYERS * (NT1 + NT2))

__global__ void wconv_kernel(const float* __restrict__ Wuv,
                             const float* __restrict__ Wout,
                             __half* __restrict__ wuvh,
                             __half* __restrict__ woh) {
    int idx = blockIdx.x;
    int layer = idx / (NT1 + NT2);
    int r = idx % (NT1 + NT2);
    const float* in; __half* oh; int K, N, nb, kb;
    if (r < NT1) {
        K = HD; N = UVQK; nb = r % (UVQK / 32); kb = r / (UVQK / 32);
        in = Wuv + (size_t)layer * HD * UVQK;
        oh = wuvh + (size_t)layer * HD * UVQK;
    } else {
        r -= NT1;
        K = ED; N = HD; nb = r % (HD / 32); kb = r / (HD / 32);
        in = Wout + (size_t)layer * ED * HD;
        oh = woh + (size_t)layer * ED * HD;
    }
    __shared__ float tile[32][33];
    int n0 = nb * 32, k0 = kb * 32;
    int tx = threadIdx.x, ty = threadIdx.y;
    #pragma unroll
    for (int i = 0; i < 4; i++)
        tile[ty + i * 8][tx] = in[(size_t)(k0 + ty + i * 8) * N + n0 + tx];
    __syncthreads();
    #pragma unroll
    for (int i = 0; i < 4; i++) {
        int n = n0 + ty + i * 8, k = k0 + tx;
        oh[(size_t)n * K + k] = __float2half(tile[tx][ty + i * 8]);
    }
}

// ---------------------------------------------------------------------------
// v: silu + transpose + fp16.  vT[b][n][k] = silu(uvqk[(b*256+k)][1536+n])
// ---------------------------------------------------------------------------
__global__ void vt_kernel(const float* __restrict__ uvqk,
                          __half* __restrict__ oh) {
    __shared__ float tile[32][33];
    int n0 = blockIdx.x * 32, k0 = blockIdx.y * 32, b = blockIdx.z;
    int tx = threadIdx.x, ty = threadIdx.y;
    #pragma unroll
    for (int i = 0; i < 4; i++) {
        int k = k0 + ty + i * 8;
        float v = uvqk[(size_t)(b * 256 + k) * UVQK + ED + n0 + tx];
        tile[ty + i * 8][tx] = v / (1.f + expf(-v));
    }
    __syncthreads();
    #pragma unroll
    for (int i = 0; i < 4; i++) {
        int n = n0 + ty + i * 8, k = k0 + tx;
        oh[((size_t)b * ED + n) * LTOK + k] = __float2half(tile[tx][ty + i * 8]);
    }
}

// ---------------------------------------------------------------------------
// Patchify + patch_W GEMM + time-embedding bias (validated round 1).
// ---------------------------------------------------------------------------
__global__ void patch_kernel(const float* __restrict__ x,
                             const int*   __restrict__ t_idx,
                             const float* __restrict__ pw,
                             const float* __restrict__ temb) {
    int r = blockIdx.x;
    int b = r >> 8, l = r & 255;
    int gy = l >> 4, gx = l & 15;
    int t = threadIdx.x;
    __shared__ float xr[PDIM];
    if (t < PDIM) {
        int py = t / 24, rem = t % 24, px = rem / 3, c = rem % 3;
        xr[t] = x[(((size_t)(b * 3 + c) * 128) + (gy * 8 + py)) * 128 + gx * 8 + px];
    }
    __syncthreads();
    const float* bias = temb + (size_t)t_idx[b] * HD;
    for (int col = t; col < HD; col += 256) {
        float s = 0.f;
        #pragma unroll 4
        for (int k = 0; k < PDIM; k++) s += xr[k] * pw[(size_t)k * HD + col];
        g_h[(size_t)r * HD + col] = s + bias[col];
    }
}

// ---------------------------------------------------------------------------
// RMSNorm: fp32 out + fp16 out.
// ---------------------------------------------------------------------------
__global__ void rmsnorm_kernel(const float* __restrict__ in,
                               const float* __restrict__ w,
                               float* __restrict__ outp,
                               __half* __restrict__ oh) {
    int r = blockIdx.x, t = threadIdx.x;
    const float* row = in + (size_t)r * HD;
    float v0 = row[t], v1 = row[t + 256], v2 = row[t + 512];
    __shared__ float red[256];
    red[t] = v0 * v0 + v1 * v1 + v2 * v2;
    __syncthreads();
    for (int o = 128; o > 0; o >>= 1) {
        if (t < o) red[t] += red[t + o];
        __syncthreads();
    }
    float inv = 1.f / (sqrtf(red[0] * (1.0f / HD)) + 1e-6f);
    size_t base = (size_t)r * HD;
    #pragma unroll
    for (int i = 0; i < 3; i++) {
        int c = t + i * 256;
        float v = (i == 0 ? v0 : i == 1 ? v1 : v2) * inv * w[c];
        outp[base + c] = v;
        oh[base + c] = __float2half(v);
    }
}

// ---------------------------------------------------------------------------
// RoPE in place on q,k cols of uvqk (validated round 1).
// ---------------------------------------------------------------------------
__global__ void rope_kernel(float* __restrict__ uvqk) {
    int r = blockIdx.x, j = threadIdx.x;        // 64 threads
    float* row = uvqk + (size_t)r * UVQK;
    int l = r & 255;
    float p1 = (float)(l >> 4), p2 = (float)(l & 15);
    int jj = (j < 32) ? j : j - 32;
    float f  = expf(-6.907755278982137f * (float)jj * (1.0f / 31.0f));
    float a1 = p1 * f, a2 = p2 * f;
    float sv = (j < 32) ? sinf(a1) : cosf(a1);
    float cv = (j < 32) ? sinf(a2) : cosf(a2);
    float q1 = row[3072 + j], q2 = row[3136 + j];
    row[3072 + j] = q1 * cv - q2 * sv;
    row[3136 + j] = q2 * cv + q1 * sv;
    float k1 = row[3200 + j], k2 = row[3264 + j];
    row[3200 + j] = k1 * cv - k2 * sv;
    row[3264 + j] = k2 * cv + k1 * sv;
}

// ---------------------------------------------------------------------------
// Attention scores + softmax, fp16 output (validated math round 1).
// ---------------------------------------------------------------------------
__global__ void attn_kernel(const float* __restrict__ uvqk,
                            __half* __restrict__ ah) {
    int r = blockIdx.x;
    int b = r >> 8;
    int t = threadIdx.x;
    __shared__ float qs[KDIM];
    __shared__ float red[256];
    const float* qrow = uvqk + (size_t)r * UVQK + 3072;
    if (t < KDIM) qs[t] = qrow[t];
    __syncthreads();
    const float* krow = uvqk + (size_t)(b * 256 + t) * UVQK + 3200;
    float s = 0.f;
    #pragma unroll 8
    for (int j = 0; j < KDIM; j++) s += qs[j] * krow[j];
    s *= 0.08838834764831845f;
    red[t] = s; __syncthreads();
    for (int o = 128; o > 0; o >>= 1) {
        if (t < o) red[t] = fmaxf(red[t], red[t + o]);
        __syncthreads();
    }
    float mx = red[0];
    __syncthreads();
    float e = expf(s - mx);
    red[t] = e; __syncthreads();
    for (int o = 128; o > 0; o >>= 1) {
        if (t < o) red[t] += red[t + o];
        __syncthreads();
    }
    ah[(size_t)r * 256 + t] = __float2half(e / red[0]);
}

// ---------------------------------------------------------------------------
// Final unpatch (validated round 1).
// ---------------------------------------------------------------------------
__global__ void unpatch_kernel(const float* __restrict__ uw, float* __restrict__ out) {
    int r = blockIdx.x, t = threadIdx.x;
    int b = r >> 8, l = r & 255, gy = l >> 4, gx = l & 15;
    __shared__ float xr[HD];
    const float* row = g_xn + (size_t)r * HD;
    xr[t] = row[t]; xr[t + 256] = row[t + 256]; xr[t + 512] = row[t + 512];
    __syncthreads();
    if (t < PDIM) {
        float s = 0.f;
        #pragma unroll 4
        for (int k = 0; k < HD; k++) s += xr[k] * uw[(size_t)k * PDIM + t];
        int py = t / 24, rem = t % 24, px = rem / 3, c = rem % 3;
        out[(((size_t)(b * 3 + c) * 128) + (gy * 8 + py)) * 128 + gx * 8 + px] = s;
    }
}

// ---------------------------------------------------------------------------
// Host launcher
// ---------------------------------------------------------------------------
extern "C" void kernel_launch(void* const* d_in, const int* in_sizes, int n_in,
                              void* d_out, int out_size) {
    const float* x        = (const float*)d_in[0];
    const int*   t_idx    = (const int*)  d_in[1];
    const float* patch_W  = (const float*)d_in[2];
    const float* t_emb    = (const float*)d_in[3];
    const float* Wuv      = (const float*)d_in[4];
    const float* Wout     = (const float*)d_in[5];
    const float* gnorm    = (const float*)d_in[6];
    const float* fnorm_w  = (const float*)d_in[7];
    const float* unpatchW = (const float*)d_in[8];
    float* out = (float*)d_out;

    float *h, *xn, *uvqk;
    __half *xnh, *ath, *vth, *oh, *wuvh, *woh;
    cudaGetSymbolAddress((void**)&h,    g_h);
    cudaGetSymbolAddress((void**)&xn,   g_xn);
    cudaGetSymbolAddress((void**)&xnh,  g_xnh);
    cudaGetSymbolAddress((void**)&uvqk, g_uvqk);
    cudaGetSymbolAddress((void**)&ath,  g_attnh);
    cudaGetSymbolAddress((void**)&vth,  g_vth);
    cudaGetSymbolAddress((void**)&oh,   g_oh);
    cudaGetSymbolAddress((void**)&wuvh, g_wuvh);
    cudaGetSymbolAddress((void**)&woh,  g_woh);

    cudaFuncSetAttribute(mma_gemm<0>, cudaFuncAttributeMaxDynamicSharedMemorySize, GSMEM_SZ);
    cudaFuncSetAttribute(mma_gemm<1>, cudaFuncAttributeMaxDynamicSharedMemorySize, GSMEM_SZ);
    cudaFuncSetAttribute(mma_gemm<2>, cudaFuncAttributeMaxDynamicSharedMemorySize, GSMEM_SZ);

    // launch 0: merged weight transpose + fp16 convert
    wconv_kernel<<<WCONV_GRID, dim3(32, 8)>>>(Wuv, Wout, wuvh, woh);

    // launch 1
    patch_kernel<<<ROWS, 256>>>(x, t_idx, patch_W, t_emb);

    for (int l = 0; l < NLAYERS; l++) {
        // launch 2 (first iter)
        rmsnorm_kernel<<<ROWS, 256>>>(h, gnorm + (size_t)l * HD, xn, xnh);

        // launch 3 (first iter) -> ncu-captured: uvqk = xn @ Wuv[l]
        mma_gemm<0><<<dim3(UVQK / 128, ROWS / 128, 1), 256, GSMEM_SZ>>>(
            xnh, wuvh + (size_t)l * UVQK * HD,
            uvqk, nullptr, nullptr,
            HD, HD, HD, UVQK, 0, 0, 0, 0, 0, 0, 0);

        rope_kernel<<<ROWS, 64>>>(uvqk);
        attn_kernel<<<ROWS, 256>>>(uvqk, ath);
        vt_kernel<<<dim3(ED / 32, LTOK / 32, NB), dim3(32, 8)>>>(uvqk, vth);

        // o = silu(u) * (attn @ v)   per batch (256 x 1536 x 256), fused epilogue
        mma_gemm<1><<<dim3(ED / 128, LTOK / 128, NB), 256, GSMEM_SZ>>>(
            ath, vth,
            nullptr, uvqk, oh,
            LTOK, LTOK, LTOK, 0, UVQK, ED,
            (long)LTOK * LTOK, (long)ED * LTOK, 0, (long)LTOK * UVQK, (long)LTOK * ED);

        // h += o @ Wout[l]   (4096 x 768 x 1536), fused residual
        mma_gemm<2><<<dim3(HD / 128, ROWS / 128, 1), 256, GSMEM_SZ>>>(
            oh, woh + (size_t)l * HD * ED,
            h, nullptr, nullptr,
            ED, ED, ED, HD, 0, 0, 0, 0, 0, 0, 0);
    }

    rmsnorm_kernel<<<ROWS, 256>>>(h, fnorm_w, xn, xnh);
    unpatch_kernel<<<ROWS, 256>>>(unpatchW, out);
}

// round 9
// speedup vs baseline: 3.3159x; 3.3159x over previous
#include <cuda_runtime.h>
#include <cuda_fp16.h>
#include <cstdint>
#include <cstddef>

// ---------------------------------------------------------------------------
// GAU denoising model. fp16 HMMA (mma.sync) GEMMs, fp32 elsewhere.
// Round 9: QK^T moved onto the MMA path (rope -> fp16 q/k, batched HMMA
// scores GEMM, dedicated softmax kernel). attn_kernel's scalar-load dot
// product is gone.
// B=16, L=256 tokens, PD=192, H=768, E=1536, K=128, NL=24, rows=4096.
// ---------------------------------------------------------------------------

#define NB      16
#define LTOK    256
#define HD      768
#define ED      1536
#define KDIM    128
#define UVQK    3328
#define ROWS    4096
#define NLAYERS 24
#define PDIM    192

// ----- scratch (device globals; allocation is forbidden) --------------------
__device__ float g_h   [(size_t)ROWS * HD];
__device__ float g_xn  [(size_t)ROWS * HD];
__device__ __half g_xnh[(size_t)ROWS * HD];
__device__ float g_uvqk[(size_t)ROWS * UVQK];
__device__ __half g_qh [(size_t)ROWS * KDIM];      // rope'd q, fp16
__device__ __half g_kh [(size_t)ROWS * KDIM];      // rope'd k, fp16
__device__ float g_attnf[(size_t)ROWS * LTOK];     // raw qk^T scores
__device__ __half g_attnh[(size_t)ROWS * LTOK];    // softmax probs
__device__ __half g_vth[(size_t)NB * ED * LTOK];   // silu(v)^T per batch [E][L]
__device__ __half g_oh [(size_t)ROWS * ED];        // silu(u)*av
__device__ __half g_wuvh[(size_t)NLAYERS * UVQK * HD];   // Wuv^T [N][K]
__device__ __half g_woh [(size_t)NLAYERS * HD * ED];     // Wout^T [N][K]

// ---------------------------------------------------------------------------
// PTX helpers (sm_80-era; compile for base sm_100)
// ---------------------------------------------------------------------------
__device__ __forceinline__ uint32_t smem_u32(const void* p) {
    uint32_t a;
    asm("{ .reg .u64 t; cvta.to.shared.u64 t, %1; cvt.u32.u64 %0, t; }"
        : "=r"(a) : "l"(p));
    return a;
}
__device__ __forceinline__ void cp16(uint32_t dst, const void* src) {
    asm volatile("cp.async.cg.shared.global [%0], [%1], 16;"
                 :: "r"(dst), "l"(src) : "memory");
}
#define CP_COMMIT() asm volatile("cp.async.commit_group;" ::: "memory")
#define CP_WAIT(N)  asm volatile("cp.async.wait_group %0;" :: "n"(N) : "memory")

__device__ __forceinline__ void ldsm4(uint32_t* r, uint32_t addr) {
    asm volatile("ldmatrix.sync.aligned.m8n8.x4.shared.b16 {%0,%1,%2,%3}, [%4];"
                 : "=r"(r[0]), "=r"(r[1]), "=r"(r[2]), "=r"(r[3]) : "r"(addr));
}
__device__ __forceinline__ void mma16816(float* c, const uint32_t* a,
                                         uint32_t b0, uint32_t b1) {
    asm volatile(
        "mma.sync.aligned.m16n8k16.row.col.f32.f16.f16.f32 "
        "{%0,%1,%2,%3}, {%4,%5,%6,%7}, {%8,%9}, {%0,%1,%2,%3};"
        : "+f"(c[0]), "+f"(c[1]), "+f"(c[2]), "+f"(c[3])
        : "r"(a[0]), "r"(a[1]), "r"(a[2]), "r"(a[3]), "r"(b0), "r"(b1));
}

// ---------------------------------------------------------------------------
// fp16 GEMM via mma.sync. C[M,N] from A[M,K] (row-major) and B[N,K] (K-major).
// CTA tile 128x128, BK=64, 8 warps (2m x 4n), warp tile 64x32.
// Smem tile: 128 rows x 64 halves (128B/row), 8-way XOR swizzle on 16B chunks:
//   phys(r, c) = r*128 + ((c ^ (r&7)) << 4)          (c = k-chunk 0..7)
// k-step ks (16 halves) flips chunk bits: off(ks) = off(0) ^ (ks << 5).
// 3-stage cp.async pipeline (2 stages in flight behind compute).
// EPI 0: C = D        EPI 1: O = silu(U)*D -> fp16      EPI 2: C += D
// ---------------------------------------------------------------------------
#define TILE_B   16384                   // 128 rows x 128 B
#define O_A      0
#define O_B      (TILE_B)
#define STAGE_B  (2 * TILE_B)            // 32768 B
#define NSTAGE   3
#define GSMEM_SZ (NSTAGE * STAGE_B)      // 98304 B

__device__ __forceinline__ uint32_t swz64(uint32_t r, uint32_t c) {
    return r * 128u + ((c ^ (r & 7u)) << 4);
}

template <int EPI>
__global__ void __launch_bounds__(256, 2) mma_gemm(
    const __half* __restrict__ A, const __half* __restrict__ B,
    float* __restrict__ C, const float* __restrict__ U,
    __half* __restrict__ Oh,
    int K, int lda, int ldb, int ldc, int ldu, int ldo,
    long sA, long sB, long sC, long sU, long sO) {

    extern __shared__ char smem[];
    uint32_t sb = smem_u32(smem);
    int t = threadIdx.x, lane = t & 31, wid = t >> 5;
    int wm = (wid >> 2) * 64, wn = (wid & 3) * 32;
    int bn0 = blockIdx.x * 128, bm0 = blockIdx.y * 128;
    long z = blockIdx.z;
    A += z * sA; B += z * sB;
    if (EPI != 1) C += z * sC;
    if (EPI == 1) { U += z * sU; Oh += z * sO; }

    float acc[4][4][4] = {};            // [mtile][ntile][c0..c3]

    // Per-thread loader offsets: 1024 16B-chunks per tile, 4 per thread.
    uint32_t ld_row[4], ld_c[4], ld_d[4];
    #pragma unroll
    for (int i = 0; i < 4; i++) {
        int id = t + i * 256;
        ld_row[i] = (uint32_t)(id >> 3);
        ld_c[i]   = (uint32_t)(id & 7);
        ld_d[i]   = swz64(ld_row[i], ld_c[i]);
    }

    auto load_stage = [&](int buf, int kt) {
        uint32_t base = sb + buf * STAGE_B;
        #pragma unroll
        for (int i = 0; i < 4; i++)
            cp16(base + O_A + ld_d[i],
                 A + (size_t)(bm0 + ld_row[i]) * lda + kt + ld_c[i] * 8);
        #pragma unroll
        for (int i = 0; i < 4; i++)
            cp16(base + O_B + ld_d[i],
                 B + (size_t)(bn0 + ld_row[i]) * ldb + kt + ld_c[i] * 8);
        CP_COMMIT();
    };

    // ldsm offsets for k-step 0; k-step ks is offset ^ (ks<<5).
    uint32_t aoff[4], boff[2];
    {
        uint32_t ac = (uint32_t)(lane >> 4);                // A k-chunk (0..1)
        uint32_t ar = (uint32_t)(wm + (lane & 15));
        #pragma unroll
        for (int mt = 0; mt < 4; mt++) aoff[mt] = swz64(ar + mt * 16, ac);
        uint32_t bc = (uint32_t)((lane >> 3) & 1);          // B k-chunk (0..1)
        uint32_t br = (uint32_t)(wn + ((lane >> 4) << 3) + (lane & 7));
        #pragma unroll
        for (int ntp = 0; ntp < 2; ntp++) boff[ntp] = swz64(br + ntp * 16, bc);
    }

    int nk = K / 64;
    load_stage(0, 0);
    if (nk > 1) load_stage(1, 64);
    else        CP_COMMIT();

    for (int s = 0; s < nk; s++) {
        CP_WAIT(1);                      // stage s resident; s+1 in flight
        __syncthreads();                 // everyone done reading stage s-1
        if (s + 2 < nk) load_stage((s + 2) % NSTAGE, (s + 2) * 64);
        else            CP_COMMIT();     // keep group accounting for the tail

        uint32_t base = sb + (s % NSTAGE) * STAGE_B;
        #pragma unroll
        for (int ks = 0; ks < 4; ks++) {
            uint32_t kx = (uint32_t)ks << 5;
            uint32_t bf[8];
            #pragma unroll
            for (int ntp = 0; ntp < 2; ntp++)
                ldsm4(bf + ntp * 4, base + O_B + (boff[ntp] ^ kx));
            #pragma unroll
            for (int mt = 0; mt < 4; mt++) {
                uint32_t af[4];
                ldsm4(af, base + O_A + (aoff[mt] ^ kx));
                #pragma unroll
                for (int nt = 0; nt < 4; nt++)
                    mma16816(acc[mt][nt], af, bf[nt * 2], bf[nt * 2 + 1]);
            }
        }
    }

    // -------- epilogue: direct fragment stores (32B sector per segment) -----
    int g = lane >> 2, tc = lane & 3;
    #pragma unroll
    for (int mt = 0; mt < 4; mt++) {
        #pragma unroll
        for (int nt = 0; nt < 4; nt++) {
            float* c = acc[mt][nt];
            int r0 = bm0 + wm + mt * 16 + g;
            int c0 = bn0 + wn + nt * 8 + tc * 2;
            #pragma unroll
            for (int half = 0; half < 2; half++) {
                int r = r0 + half * 8;
                float v0 = c[half * 2], v1 = c[half * 2 + 1];
                if (EPI == 0) {
                    float2 st = {v0, v1};
                    *(float2*)&C[(size_t)r * ldc + c0] = st;
                } else if (EPI == 1) {
                    const float* up = &U[(size_t)r * ldu + c0];
                    float u0 = up[0], u1 = up[1];
                    float o0 = (u0 / (1.f + expf(-u0))) * v0;
                    float o1 = (u1 / (1.f + expf(-u1))) * v1;
                    __half2 hp;
                    hp.x = __float2half(o0);
                    hp.y = __float2half(o1);
                    *(__half2*)&Oh[(size_t)r * ldo + c0] = hp;
                } else {
                    float2* p = (float2*)&C[(size_t)r * ldc + c0];
                    float2 old = *p;
                    old.x += v0; old.y += v1;
                    *p = old;
                }
            }
        }
    }
}

// ---------------------------------------------------------------------------
// Merged weight transpose + fp16 convert (one launch; keeps gemm0 at idx 3).
// ---------------------------------------------------------------------------
#define NT1 ((UVQK / 32) * (HD / 32))
#define NT2 ((HD / 32) * (ED / 32))
#define WCONV_GRID (NLAYERS * (NT1 + NT2))

__global__ void wconv_kernel(const float* __restrict__ Wuv,
                             const float* __restrict__ Wout,
                             __half* __restrict__ wuvh,
                             __half* __restrict__ woh) {
    int idx = blockIdx.x;
    int layer = idx / (NT1 + NT2);
    int r = idx % (NT1 + NT2);
    const float* in; __half* oh; int K, N, nb, kb;
    if (r < NT1) {
        K = HD; N = UVQK; nb = r % (UVQK / 32); kb = r / (UVQK / 32);
        in = Wuv + (size_t)layer * HD * UVQK;
        oh = wuvh + (size_t)layer * HD * UVQK;
    } else {
        r -= NT1;
        K = ED; N = HD; nb = r % (HD / 32); kb = r / (HD / 32);
        in = Wout + (size_t)layer * ED * HD;
        oh = woh + (size_t)layer * ED * HD;
    }
    __shared__ float tile[32][33];
    int n0 = nb * 32, k0 = kb * 32;
    int tx = threadIdx.x, ty = threadIdx.y;
    #pragma unroll
    for (int i = 0; i < 4; i++)
        tile[ty + i * 8][tx] = in[(size_t)(k0 + ty + i * 8) * N + n0 + tx];
    __syncthreads();
    #pragma unroll
    for (int i = 0; i < 4; i++) {
        int n = n0 + ty + i * 8, k = k0 + tx;
        oh[(size_t)n * K + k] = __float2half(tile[tx][ty + i * 8]);
    }
}

// ---------------------------------------------------------------------------
// v: silu + transpose + fp16.  vT[b][n][k] = silu(uvqk[(b*256+k)][1536+n])
// ---------------------------------------------------------------------------
__global__ void vt_kernel(const float* __restrict__ uvqk,
                          __half* __restrict__ oh) {
    __shared__ float tile[32][33];
    int n0 = blockIdx.x * 32, k0 = blockIdx.y * 32, b = blockIdx.z;
    int tx = threadIdx.x, ty = threadIdx.y;
    #pragma unroll
    for (int i = 0; i < 4; i++) {
        int k = k0 + ty + i * 8;
        float v = uvqk[(size_t)(b * 256 + k) * UVQK + ED + n0 + tx];
        tile[ty + i * 8][tx] = v / (1.f + expf(-v));
    }
    __syncthreads();
    #pragma unroll
    for (int i = 0; i < 4; i++) {
        int n = n0 + ty + i * 8, k = k0 + tx;
        oh[((size_t)b * ED + n) * LTOK + k] = __float2half(tile[tx][ty + i * 8]);
    }
}

// ---------------------------------------------------------------------------
// Patchify + patch_W GEMM + time-embedding bias (validated round 1).
// ---------------------------------------------------------------------------
__global__ void patch_kernel(const float* __restrict__ x,
                             const int*   __restrict__ t_idx,
                             const float* __restrict__ pw,
                             const float* __restrict__ temb) {
    int r = blockIdx.x;
    int b = r >> 8, l = r & 255;
    int gy = l >> 4, gx = l & 15;
    int t = threadIdx.x;
    __shared__ float xr[PDIM];
    if (t < PDIM) {
        int py = t / 24, rem = t % 24, px = rem / 3, c = rem % 3;
        xr[t] = x[(((size_t)(b * 3 + c) * 128) + (gy * 8 + py)) * 128 + gx * 8 + px];
    }
    __syncthreads();
    const float* bias = temb + (size_t)t_idx[b] * HD;
    for (int col = t; col < HD; col += 256) {
        float s = 0.f;
        #pragma unroll 4
        for (int k = 0; k < PDIM; k++) s += xr[k] * pw[(size_t)k * HD + col];
        g_h[(size_t)r * HD + col] = s + bias[col];
    }
}

// ---------------------------------------------------------------------------
// RMSNorm: fp32 out + fp16 out.
// ---------------------------------------------------------------------------
__global__ void rmsnorm_kernel(const float* __restrict__ in,
                               const float* __restrict__ w,
                               float* __restrict__ outp,
                               __half* __restrict__ oh) {
    int r = blockIdx.x, t = threadIdx.x;
    const float* row = in + (size_t)r * HD;
    float v0 = row[t], v1 = row[t + 256], v2 = row[t + 512];
    __shared__ float red[256];
    red[t] = v0 * v0 + v1 * v1 + v2 * v2;
    __syncthreads();
    for (int o = 128; o > 0; o >>= 1) {
        if (t < o) red[t] += red[t + o];
        __syncthreads();
    }
    float inv = 1.f / (sqrtf(red[0] * (1.0f / HD)) + 1e-6f);
    size_t base = (size_t)r * HD;
    #pragma unroll
    for (int i = 0; i < 3; i++) {
        int c = t + i * 256;
        float v = (i == 0 ? v0 : i == 1 ? v1 : v2) * inv * w[c];
        outp[base + c] = v;
        oh[base + c] = __float2half(v);
    }
}

// ---------------------------------------------------------------------------
// RoPE: read q,k cols of uvqk, apply rope (validated math), write fp16 q/k.
// ---------------------------------------------------------------------------
__global__ void rope_kernel(const float* __restrict__ uvqk,
                            __half* __restrict__ qh,
                            __half* __restrict__ kh) {
    int r = blockIdx.x, j = threadIdx.x;        // 64 threads
    const float* row = uvqk + (size_t)r * UVQK;
    int l = r & 255;
    float p1 = (float)(l >> 4), p2 = (float)(l & 15);
    int jj = (j < 32) ? j : j - 32;
    float f  = expf(-6.907755278982137f * (float)jj * (1.0f / 31.0f));
    float a1 = p1 * f, a2 = p2 * f;
    float sv = (j < 32) ? sinf(a1) : cosf(a1);
    float cv = (j < 32) ? sinf(a2) : cosf(a2);
    float q1 = row[3072 + j], q2 = row[3136 + j];
    qh[(size_t)r * KDIM + j]      = __float2half(q1 * cv - q2 * sv);
    qh[(size_t)r * KDIM + j + 64] = __float2half(q2 * cv + q1 * sv);
    float k1 = row[3200 + j], k2 = row[3264 + j];
    kh[(size_t)r * KDIM + j]      = __float2half(k1 * cv - k2 * sv);
    kh[(size_t)r * KDIM + j + 64] = __float2half(k2 * cv + k1 * sv);
}

// ---------------------------------------------------------------------------
// Softmax over raw scores (fp32, row of 256) -> fp16 probs.
// Scale applied here. Same validated reduction tree as before.
// ---------------------------------------------------------------------------
__global__ void softmax_kernel(const float* __restrict__ sc,
                               __half* __restrict__ ah) {
    int r = blockIdx.x, t = threadIdx.x;
    __shared__ float red[256];
    float s = sc[(size_t)r * 256 + t] * 0.08838834764831845f;
    red[t] = s; __syncthreads();
    for (int o = 128; o > 0; o >>= 1) {
        if (t < o) red[t] = fmaxf(red[t], red[t + o]);
        __syncthreads();
    }
    float mx = red[0];
    __syncthreads();
    float e = expf(s - mx);
    red[t] = e; __syncthreads();
    for (int o = 128; o > 0; o >>= 1) {
        if (t < o) red[t] += red[t + o];
        __syncthreads();
    }
    ah[(size_t)r * 256 + t] = __float2half(e / red[0]);
}

// ---------------------------------------------------------------------------
// Final unpatch (validated round 1).
// ---------------------------------------------------------------------------
__global__ void unpatch_kernel(const float* __restrict__ uw, float* __restrict__ out) {
    int r = blockIdx.x, t = threadIdx.x;
    int b = r >> 8, l = r & 255, gy = l >> 4, gx = l & 15;
    __shared__ float xr[HD];
    const float* row = g_xn + (size_t)r * HD;
    xr[t] = row[t]; xr[t + 256] = row[t + 256]; xr[t + 512] = row[t + 512];
    __syncthreads();
    if (t < PDIM) {
        float s = 0.f;
        #pragma unroll 4
        for (int k = 0; k < HD; k++) s += xr[k] * uw[(size_t)k * PDIM + t];
        int py = t / 24, rem = t % 24, px = rem / 3, c = rem % 3;
        out[(((size_t)(b * 3 + c) * 128) + (gy * 8 + py)) * 128 + gx * 8 + px] = s;
    }
}

// ---------------------------------------------------------------------------
// Host launcher
// ---------------------------------------------------------------------------
extern "C" void kernel_launch(void* const* d_in, const int* in_sizes, int n_in,
                              void* d_out, int out_size) {
    const float* x        = (const float*)d_in[0];
    const int*   t_idx    = (const int*)  d_in[1];
    const float* patch_W  = (const float*)d_in[2];
    const float* t_emb    = (const float*)d_in[3];
    const float* Wuv      = (const float*)d_in[4];
    const float* Wout     = (const float*)d_in[5];
    const float* gnorm    = (const float*)d_in[6];
    const float* fnorm_w  = (const float*)d_in[7];
    const float* unpatchW = (const float*)d_in[8];
    float* out = (float*)d_out;

    float *h, *xn, *uvqk, *attnf;
    __half *xnh, *qh, *kh, *ath, *vth, *oh, *wuvh, *woh;
    cudaGetSymbolAddress((void**)&h,     g_h);
    cudaGetSymbolAddress((void**)&xn,    g_xn);
    cudaGetSymbolAddress((void**)&xnh,   g_xnh);
    cudaGetSymbolAddress((void**)&uvqk,  g_uvqk);
    cudaGetSymbolAddress((void**)&qh,    g_qh);
    cudaGetSymbolAddress((void**)&kh,    g_kh);
    cudaGetSymbolAddress((void**)&attnf, g_attnf);
    cudaGetSymbolAddress((void**)&ath,   g_attnh);
    cudaGetSymbolAddress((void**)&vth,   g_vth);
    cudaGetSymbolAddress((void**)&oh,    g_oh);
    cudaGetSymbolAddress((void**)&wuvh,  g_wuvh);
    cudaGetSymbolAddress((void**)&woh,   g_woh);

    cudaFuncSetAttribute(mma_gemm<0>, cudaFuncAttributeMaxDynamicSharedMemorySize, GSMEM_SZ);
    cudaFuncSetAttribute(mma_gemm<1>, cudaFuncAttributeMaxDynamicSharedMemorySize, GSMEM_SZ);
    cudaFuncSetAttribute(mma_gemm<2>, cudaFuncAttributeMaxDynamicSharedMemorySize, GSMEM_SZ);

    // launch 0: merged weight transpose + fp16 convert
    wconv_kernel<<<WCONV_GRID, dim3(32, 8)>>>(Wuv, Wout, wuvh, woh);

    // launch 1
    patch_kernel<<<ROWS, 256>>>(x, t_idx, patch_W, t_emb);

    for (int l = 0; l < NLAYERS; l++) {
        // launch 2 (first iter)
        rmsnorm_kernel<<<ROWS, 256>>>(h, gnorm + (size_t)l * HD, xn, xnh);

        // launch 3 (first iter) -> ncu-captured: uvqk = xn @ Wuv[l]
        mma_gemm<0><<<dim3(UVQK / 128, ROWS / 128, 1), 256, GSMEM_SZ>>>(
            xnh, wuvh + (size_t)l * UVQK * HD,
            uvqk, nullptr, nullptr,
            HD, HD, HD, UVQK, 0, 0, 0, 0, 0, 0, 0);

        rope_kernel<<<ROWS, 64>>>(uvqk, qh, kh);

        // scores = q @ k^T  per batch (256 x 256 x 128)
        mma_gemm<0><<<dim3(LTOK / 128, LTOK / 128, NB), 256, GSMEM_SZ>>>(
            qh, kh,
            attnf, nullptr, nullptr,
            KDIM, KDIM, KDIM, LTOK, 0, 0,
            (long)LTOK * KDIM, (long)LTOK * KDIM, (long)LTOK * LTOK, 0, 0);

        softmax_kernel<<<ROWS, 256>>>(attnf, ath);
        vt_kernel<<<dim3(ED / 32, LTOK / 32, NB), dim3(32, 8)>>>(uvqk, vth);

        // o = silu(u) * (attn @ v)   per batch (256 x 1536 x 256), fused epilogue
        mma_gemm<1><<<dim3(ED / 128, LTOK / 128, NB), 256, GSMEM_SZ>>>(
            ath, vth,
            nullptr, uvqk, oh,
            LTOK, LTOK, LTOK, 0, UVQK, ED,
            (long)LTOK * LTOK, (long)ED * LTOK, 0, (long)LTOK * UVQK, (long)LTOK * ED);

        // h += o @ Wout[l]   (4096 x 768 x 1536), fused residual
        mma_gemm<2><<<dim3(HD / 128, ROWS / 128, 1), 256, GSMEM_SZ>>>(
            oh, woh + (size_t)l * HD * ED,
            h, nullptr, nullptr,
            ED, ED, ED, HD, 0, 0, 0, 0, 0, 0, 0);
    }

    rmsnorm_kernel<<<ROWS, 256>>>(h, fnorm_w, xn, xnh);
    unpatch_kernel<<<ROWS, 256>>>(unpatchW, out);
}

// round 10
// speedup vs baseline: 3.4681x; 1.0459x over previous
#include <cuda_runtime.h>
#include <cuda_fp16.h>
#include <cstdint>
#include <cstddef>

// ---------------------------------------------------------------------------
// GAU denoising model. fp16 HMMA (mma.sync) GEMMs, fp32 elsewhere.
// Round 10: GEMM inner loop issues all fragment ldsm up front per k-step
// (one dependency stall instead of four); shuffle reductions in
// rmsnorm/softmax; rope+vt merged into one launch.
// B=16, L=256 tokens, PD=192, H=768, E=1536, K=128, NL=24, rows=4096.
// ---------------------------------------------------------------------------

#define NB      16
#define LTOK    256
#define HD      768
#define ED      1536
#define KDIM    128
#define UVQK    3328
#define ROWS    4096
#define NLAYERS 24
#define PDIM    192

// ----- scratch (device globals; allocation is forbidden) --------------------
__device__ float g_h   [(size_t)ROWS * HD];
__device__ float g_xn  [(size_t)ROWS * HD];
__device__ __half g_xnh[(size_t)ROWS * HD];
__device__ float g_uvqk[(size_t)ROWS * UVQK];
__device__ __half g_qh [(size_t)ROWS * KDIM];      // rope'd q, fp16
__device__ __half g_kh [(size_t)ROWS * KDIM];      // rope'd k, fp16
__device__ float g_attnf[(size_t)ROWS * LTOK];     // raw qk^T scores
__device__ __half g_attnh[(size_t)ROWS * LTOK];    // softmax probs
__device__ __half g_vth[(size_t)NB * ED * LTOK];   // silu(v)^T per batch [E][L]
__device__ __half g_oh [(size_t)ROWS * ED];        // silu(u)*av
__device__ __half g_wuvh[(size_t)NLAYERS * UVQK * HD];   // Wuv^T [N][K]
__device__ __half g_woh [(size_t)NLAYERS * HD * ED];     // Wout^T [N][K]

// ---------------------------------------------------------------------------
// PTX helpers (sm_80-era; compile for base sm_100)
// ---------------------------------------------------------------------------
__device__ __forceinline__ uint32_t smem_u32(const void* p) {
    uint32_t a;
    asm("{ .reg .u64 t; cvta.to.shared.u64 t, %1; cvt.u32.u64 %0, t; }"
        : "=r"(a) : "l"(p));
    return a;
}
__device__ __forceinline__ void cp16(uint32_t dst, const void* src) {
    asm volatile("cp.async.cg.shared.global [%0], [%1], 16;"
                 :: "r"(dst), "l"(src) : "memory");
}
#define CP_COMMIT() asm volatile("cp.async.commit_group;" ::: "memory")
#define CP_WAIT(N)  asm volatile("cp.async.wait_group %0;" :: "n"(N) : "memory")

__device__ __forceinline__ void ldsm4(uint32_t* r, uint32_t addr) {
    asm volatile("ldmatrix.sync.aligned.m8n8.x4.shared.b16 {%0,%1,%2,%3}, [%4];"
                 : "=r"(r[0]), "=r"(r[1]), "=r"(r[2]), "=r"(r[3]) : "r"(addr));
}
__device__ __forceinline__ void mma16816(float* c, const uint32_t* a,
                                         uint32_t b0, uint32_t b1) {
    asm volatile(
        "mma.sync.aligned.m16n8k16.row.col.f32.f16.f16.f32 "
        "{%0,%1,%2,%3}, {%4,%5,%6,%7}, {%8,%9}, {%0,%1,%2,%3};"
        : "+f"(c[0]), "+f"(c[1]), "+f"(c[2]), "+f"(c[3])
        : "r"(a[0]), "r"(a[1]), "r"(a[2]), "r"(a[3]), "r"(b0), "r"(b1));
}

// ---------------------------------------------------------------------------
// fp16 GEMM via mma.sync. C[M,N] from A[M,K] (row-major) and B[N,K] (K-major).
// CTA tile 128x128, BK=64, 8 warps (2m x 4n), warp tile 64x32.
// Smem tile: 128 rows x 64 halves (128B/row), 8-way XOR swizzle on 16B chunks:
//   phys(r, c) = r*128 + ((c ^ (r&7)) << 4)          (c = k-chunk 0..7)
// k-step ks flips chunk bits: off(ks) = off(0) ^ (ks << 5).
// 3-stage cp.async pipeline. Fragments for a whole k-step loaded up front.
// EPI 0: C = D        EPI 1: O = silu(U)*D -> fp16      EPI 2: C += D
// ---------------------------------------------------------------------------
#define TILE_B   16384                   // 128 rows x 128 B
#define O_A      0
#define O_B      (TILE_B)
#define STAGE_B  (2 * TILE_B)            // 32768 B
#define NSTAGE   3
#define GSMEM_SZ (NSTAGE * STAGE_B)      // 98304 B

__device__ __forceinline__ uint32_t swz64(uint32_t r, uint32_t c) {
    return r * 128u + ((c ^ (r & 7u)) << 4);
}

template <int EPI>
__global__ void __launch_bounds__(256, 2) mma_gemm(
    const __half* __restrict__ A, const __half* __restrict__ B,
    float* __restrict__ C, const float* __restrict__ U,
    __half* __restrict__ Oh,
    int K, int lda, int ldb, int ldc, int ldu, int ldo,
    long sA, long sB, long sC, long sU, long sO) {

    extern __shared__ char smem[];
    uint32_t sb = smem_u32(smem);
    int t = threadIdx.x, lane = t & 31, wid = t >> 5;
    int wm = (wid >> 2) * 64, wn = (wid & 3) * 32;
    int bn0 = blockIdx.x * 128, bm0 = blockIdx.y * 128;
    long z = blockIdx.z;
    A += z * sA; B += z * sB;
    if (EPI != 1) C += z * sC;
    if (EPI == 1) { U += z * sU; Oh += z * sO; }

    float acc[4][4][4] = {};            // [mtile][ntile][c0..c3]

    // Loader: 1024 16B-chunks per tile, 4 per thread; addresses recomputed
    // per stage (frees registers for the fragment working set).
    auto load_stage = [&](int buf, int kt) {
        uint32_t base = sb + buf * STAGE_B;
        #pragma unroll
        for (int i = 0; i < 4; i++) {
            int id = t + i * 256;
            uint32_t row = (uint32_t)(id >> 3), c = (uint32_t)(id & 7);
            uint32_t d = swz64(row, c);
            cp16(base + O_A + d, A + (size_t)(bm0 + row) * lda + kt + c * 8);
            cp16(base + O_B + d, B + (size_t)(bn0 + row) * ldb + kt + c * 8);
        }
        CP_COMMIT();
    };

    // ldsm offsets for k-step 0; k-step ks is offset ^ (ks<<5).
    uint32_t aoff[4], boff[2];
    {
        uint32_t ac = (uint32_t)(lane >> 4);                // A k-chunk (0..1)
        uint32_t ar = (uint32_t)(wm + (lane & 15));
        #pragma unroll
        for (int mt = 0; mt < 4; mt++) aoff[mt] = swz64(ar + mt * 16, ac);
        uint32_t bc = (uint32_t)((lane >> 3) & 1);          // B k-chunk (0..1)
        uint32_t br = (uint32_t)(wn + ((lane >> 4) << 3) + (lane & 7));
        #pragma unroll
        for (int ntp = 0; ntp < 2; ntp++) boff[ntp] = swz64(br + ntp * 16, bc);
    }

    int nk = K / 64;
    load_stage(0, 0);
    if (nk > 1) load_stage(1, 64);
    else        CP_COMMIT();

    for (int s = 0; s < nk; s++) {
        CP_WAIT(1);                      // stage s resident; s+1 in flight
        __syncthreads();                 // everyone done reading stage s-1
        if (s + 2 < nk) load_stage((s + 2) % NSTAGE, (s + 2) * 64);
        else            CP_COMMIT();     // keep group accounting for the tail

        uint32_t base = sb + (s % NSTAGE) * STAGE_B;
        #pragma unroll
        for (int ks = 0; ks < 4; ks++) {
            uint32_t kx = (uint32_t)ks << 5;
            uint32_t bf[8], af[4][4];
            // All fragment loads issued back-to-back (B first: first MMA
            // consumers are af[0], bf[0..1]); MIO pipelines the 6 ldsm.
            ldsm4(bf,     base + O_B + (boff[0] ^ kx));
            ldsm4(bf + 4, base + O_B + (boff[1] ^ kx));
            #pragma unroll
            for (int mt = 0; mt < 4; mt++)
                ldsm4(af[mt], base + O_A + (aoff[mt] ^ kx));
            #pragma unroll
            for (int mt = 0; mt < 4; mt++)
                #pragma unroll
                for (int nt = 0; nt < 4; nt++)
                    mma16816(acc[mt][nt], af[mt], bf[nt * 2], bf[nt * 2 + 1]);
        }
    }

    // -------- epilogue: direct fragment stores (32B sector per segment) -----
    int g = lane >> 2, tc = lane & 3;
    #pragma unroll
    for (int mt = 0; mt < 4; mt++) {
        #pragma unroll
        for (int nt = 0; nt < 4; nt++) {
            float* c = acc[mt][nt];
            int r0 = bm0 + wm + mt * 16 + g;
            int c0 = bn0 + wn + nt * 8 + tc * 2;
            #pragma unroll
            for (int half = 0; half < 2; half++) {
                int r = r0 + half * 8;
                float v0 = c[half * 2], v1 = c[half * 2 + 1];
                if (EPI == 0) {
                    float2 st = {v0, v1};
                    *(float2*)&C[(size_t)r * ldc + c0] = st;
                } else if (EPI == 1) {
                    const float* up = &U[(size_t)r * ldu + c0];
                    float u0 = up[0], u1 = up[1];
                    float o0 = (u0 / (1.f + expf(-u0))) * v0;
                    float o1 = (u1 / (1.f + expf(-u1))) * v1;
                    __half2 hp;
                    hp.x = __float2half(o0);
                    hp.y = __float2half(o1);
                    *(__half2*)&Oh[(size_t)r * ldo + c0] = hp;
                } else {
                    float2* p = (float2*)&C[(size_t)r * ldc + c0];
                    float2 old = *p;
                    old.x += v0; old.y += v1;
                    *p = old;
                }
            }
        }
    }
}

// ---------------------------------------------------------------------------
// Merged weight transpose + fp16 convert (one launch; keeps gemm0 at idx 3).
// ---------------------------------------------------------------------------
#define NT1 ((UVQK / 32) * (HD / 32))
#define NT2 ((HD / 32) * (ED / 32))
#define WCONV_GRID (NLAYERS * (NT1 + NT2))

__global__ void wconv_kernel(const float* __restrict__ Wuv,
                             const float* __restrict__ Wout,
                             __half* __restrict__ wuvh,
                             __half* __restrict__ woh) {
    int idx = blockIdx.x;
    int layer = idx / (NT1 + NT2);
    int r = idx % (NT1 + NT2);
    const float* in; __half* oh; int K, N, nb, kb;
    if (r < NT1) {
        K = HD; N = UVQK; nb = r % (UVQK / 32); kb = r / (UVQK / 32);
        in = Wuv + (size_t)layer * HD * UVQK;
        oh = wuvh + (size_t)layer * HD * UVQK;
    } else {
        r -= NT1;
        K = ED; N = HD; nb = r % (HD / 32); kb = r / (HD / 32);
        in = Wout + (size_t)layer * ED * HD;
        oh = woh + (size_t)layer * ED * HD;
    }
    __shared__ float tile[32][33];
    int n0 = nb * 32, k0 = kb * 32;
    int tx = threadIdx.x & 31, ty = threadIdx.x >> 5;
    #pragma unroll
    for (int i = 0; i < 4; i++)
        tile[ty + i * 8][tx] = in[(size_t)(k0 + ty + i * 8) * N + n0 + tx];
    __syncthreads();
    #pragma unroll
    for (int i = 0; i < 4; i++) {
        int n = n0 + ty + i * 8, k = k0 + tx;
        oh[(size_t)n * K + k] = __float2half(tile[tx][ty + i * 8]);
    }
}

// ---------------------------------------------------------------------------
// Merged rope + vt (both depend only on uvqk; one launch).
// Blocks [0, VT_BLOCKS): v silu+transpose+fp16.
// Blocks [VT_BLOCKS, +ROPE_BLOCKS): rope -> fp16 q/k (4 rows/block).
// ---------------------------------------------------------------------------
#define VT_BLOCKS   ((ED / 32) * (LTOK / 32) * NB)    // 6144
#define ROPE_BLOCKS (ROWS / 4)                         // 1024
#define RV_GRID     (VT_BLOCKS + ROPE_BLOCKS)

__global__ void ropevt_kernel(const float* __restrict__ uvqk,
                              __half* __restrict__ vth,
                              __half* __restrict__ qh,
                              __half* __restrict__ kh) {
    int t = threadIdx.x;
    if (blockIdx.x < VT_BLOCKS) {
        int r = blockIdx.x;
        int b = r / ((ED / 32) * (LTOK / 32));
        int rem = r % ((ED / 32) * (LTOK / 32));
        int n0 = (rem % (ED / 32)) * 32;
        int k0 = (rem / (ED / 32)) * 32;
        __shared__ float tile[32][33];
        int tx = t & 31, ty = t >> 5;
        #pragma unroll
        for (int i = 0; i < 4; i++) {
            int k = k0 + ty + i * 8;
            float v = uvqk[(size_t)(b * 256 + k) * UVQK + ED + n0 + tx];
            tile[ty + i * 8][tx] = v / (1.f + expf(-v));
        }
        __syncthreads();
        #pragma unroll
        for (int i = 0; i < 4; i++) {
            int n = n0 + ty + i * 8, k = k0 + tx;
            vth[((size_t)b * ED + n) * LTOK + k] = __float2half(tile[tx][ty + i * 8]);
        }
    } else {
        int idx = blockIdx.x - VT_BLOCKS;
        int r = idx * 4 + (t >> 6);
        int j = t & 63;
        const float* row = uvqk + (size_t)r * UVQK;
        int l = r & 255;
        float p1 = (float)(l >> 4), p2 = (float)(l & 15);
        int jj = (j < 32) ? j : j - 32;
        float f  = expf(-6.907755278982137f * (float)jj * (1.0f / 31.0f));
        float a1 = p1 * f, a2 = p2 * f;
        float sv = (j < 32) ? sinf(a1) : cosf(a1);
        float cv = (j < 32) ? sinf(a2) : cosf(a2);
        float q1 = row[3072 + j], q2 = row[3136 + j];
        qh[(size_t)r * KDIM + j]      = __float2half(q1 * cv - q2 * sv);
        qh[(size_t)r * KDIM + j + 64] = __float2half(q2 * cv + q1 * sv);
        float k1 = row[3200 + j], k2 = row[3264 + j];
        kh[(size_t)r * KDIM + j]      = __float2half(k1 * cv - k2 * sv);
        kh[(size_t)r * KDIM + j + 64] = __float2half(k2 * cv + k1 * sv);
    }
}

// ---------------------------------------------------------------------------
// Patchify + patch_W GEMM + time-embedding bias (validated round 1).
// ---------------------------------------------------------------------------
__global__ void patch_kernel(const float* __restrict__ x,
                             const int*   __restrict__ t_idx,
                             const float* __restrict__ pw,
                             const float* __restrict__ temb) {
    int r = blockIdx.x;
    int b = r >> 8, l = r & 255;
    int gy = l >> 4, gx = l & 15;
    int t = threadIdx.x;
    __shared__ float xr[PDIM];
    if (t < PDIM) {
        int py = t / 24, rem = t % 24, px = rem / 3, c = rem % 3;
        xr[t] = x[(((size_t)(b * 3 + c) * 128) + (gy * 8 + py)) * 128 + gx * 8 + px];
    }
    __syncthreads();
    const float* bias = temb + (size_t)t_idx[b] * HD;
    for (int col = t; col < HD; col += 256) {
        float s = 0.f;
        #pragma unroll 4
        for (int k = 0; k < PDIM; k++) s += xr[k] * pw[(size_t)k * HD + col];
        g_h[(size_t)r * HD + col] = s + bias[col];
    }
}

// ---------------------------------------------------------------------------
// RMSNorm: fp32 out + fp16 out. Shuffle reduction (2 barriers).
// ---------------------------------------------------------------------------
__global__ void rmsnorm_kernel(const float* __restrict__ in,
                               const float* __restrict__ w,
                               float* __restrict__ outp,
                               __half* __restrict__ oh) {
    int r = blockIdx.x, t = threadIdx.x;
    int lane = t & 31, wid = t >> 5;
    const float* row = in + (size_t)r * HD;
    float v0 = row[t], v1 = row[t + 256], v2 = row[t + 512];
    float ss = v0 * v0 + v1 * v1 + v2 * v2;
    #pragma unroll
    for (int o = 16; o > 0; o >>= 1) ss += __shfl_xor_sync(0xffffffffu, ss, o);
    __shared__ float wred[8];
    if (lane == 0) wred[wid] = ss;
    __syncthreads();
    float tot = wred[0];
    #pragma unroll
    for (int i = 1; i < 8; i++) tot += wred[i];
    float inv = 1.f / (sqrtf(tot * (1.0f / HD)) + 1e-6f);
    size_t base = (size_t)r * HD;
    #pragma unroll
    for (int i = 0; i < 3; i++) {
        int c = t + i * 256;
        float v = (i == 0 ? v0 : i == 1 ? v1 : v2) * inv * w[c];
        outp[base + c] = v;
        oh[base + c] = __float2half(v);
    }
}

// ---------------------------------------------------------------------------
// Softmax over raw scores (fp32, row of 256) -> fp16 probs. Shuffle reduction.
// ---------------------------------------------------------------------------
__global__ void softmax_kernel(const float* __restrict__ sc,
                               __half* __restrict__ ah) {
    int r = blockIdx.x, t = threadIdx.x;
    int lane = t & 31, wid = t >> 5;
    __shared__ float wmax[8], wsum[8];
    float s = sc[(size_t)r * 256 + t] * 0.08838834764831845f;
    float m = s;
    #pragma unroll
    for (int o = 16; o > 0; o >>= 1) m = fmaxf(m, __shfl_xor_sync(0xffffffffu, m, o));
    if (lane == 0) wmax[wid] = m;
    __syncthreads();
    float mx = wmax[0];
    #pragma unroll
    for (int i = 1; i < 8; i++) mx = fmaxf(mx, wmax[i]);
    float e = expf(s - mx);
    float su = e;
    #pragma unroll
    for (int o = 16; o > 0; o >>= 1) su += __shfl_xor_sync(0xffffffffu, su, o);
    if (lane == 0) wsum[wid] = su;
    __syncthreads();
    float tot = wsum[0];
    #pragma unroll
    for (int i = 1; i < 8; i++) tot += wsum[i];
    ah[(size_t)r * 256 + t] = __float2half(e / tot);
}

// ---------------------------------------------------------------------------
// Final unpatch (validated round 1).
// ---------------------------------------------------------------------------
__global__ void unpatch_kernel(const float* __restrict__ uw, float* __restrict__ out) {
    int r = blockIdx.x, t = threadIdx.x;
    int b = r >> 8, l = r & 255, gy = l >> 4, gx = l & 15;
    __shared__ float xr[HD];
    const float* row = g_xn + (size_t)r * HD;
    xr[t] = row[t]; xr[t + 256] = row[t + 256]; xr[t + 512] = row[t + 512];
    __syncthreads();
    if (t < PDIM) {
        float s = 0.f;
        #pragma unroll 4
        for (int k = 0; k < HD; k++) s += xr[k] * uw[(size_t)k * PDIM + t];
        int py = t / 24, rem = t % 24, px = rem / 3, c = rem % 3;
        out[(((size_t)(b * 3 + c) * 128) + (gy * 8 + py)) * 128 + gx * 8 + px] = s;
    }
}

// ---------------------------------------------------------------------------
// Host launcher
// ---------------------------------------------------------------------------
extern "C" void kernel_launch(void* const* d_in, const int* in_sizes, int n_in,
                              void* d_out, int out_size) {
    const float* x        = (const float*)d_in[0];
    const int*   t_idx    = (const int*)  d_in[1];
    const float* patch_W  = (const float*)d_in[2];
    const float* t_emb    = (const float*)d_in[3];
    const float* Wuv      = (const float*)d_in[4];
    const float* Wout     = (const float*)d_in[5];
    const float* gnorm    = (const float*)d_in[6];
    const float* fnorm_w  = (const float*)d_in[7];
    const float* unpatchW = (const float*)d_in[8];
    float* out = (float*)d_out;

    float *h, *xn, *uvqk, *attnf;
    __half *xnh, *qh, *kh, *ath, *vth, *oh, *wuvh, *woh;
    cudaGetSymbolAddress((void**)&h,     g_h);
    cudaGetSymbolAddress((void**)&xn,    g_xn);
    cudaGetSymbolAddress((void**)&xnh,   g_xnh);
    cudaGetSymbolAddress((void**)&uvqk,  g_uvqk);
    cudaGetSymbolAddress((void**)&qh,    g_qh);
    cudaGetSymbolAddress((void**)&kh,    g_kh);
    cudaGetSymbolAddress((void**)&attnf, g_attnf);
    cudaGetSymbolAddress((void**)&ath,   g_attnh);
    cudaGetSymbolAddress((void**)&vth,   g_vth);
    cudaGetSymbolAddress((void**)&oh,    g_oh);
    cudaGetSymbolAddress((void**)&wuvh,  g_wuvh);
    cudaGetSymbolAddress((void**)&woh,   g_woh);

    cudaFuncSetAttribute(mma_gemm<0>, cudaFuncAttributeMaxDynamicSharedMemorySize, GSMEM_SZ);
    cudaFuncSetAttribute(mma_gemm<1>, cudaFuncAttributeMaxDynamicSharedMemorySize, GSMEM_SZ);
    cudaFuncSetAttribute(mma_gemm<2>, cudaFuncAttributeMaxDynamicSharedMemorySize, GSMEM_SZ);

    // launch 0: merged weight transpose + fp16 convert
    wconv_kernel<<<WCONV_GRID, 256>>>(Wuv, Wout, wuvh, woh);

    // launch 1
    patch_kernel<<<ROWS, 256>>>(x, t_idx, patch_W, t_emb);

    for (int l = 0; l < NLAYERS; l++) {
        // launch 2 (first iter)
        rmsnorm_kernel<<<ROWS, 256>>>(h, gnorm + (size_t)l * HD, xn, xnh);

        // launch 3 (first iter) -> ncu-captured: uvqk = xn @ Wuv[l]
        mma_gemm<0><<<dim3(UVQK / 128, ROWS / 128, 1), 256, GSMEM_SZ>>>(
            xnh, wuvh + (size_t)l * UVQK * HD,
            uvqk, nullptr, nullptr,
            HD, HD, HD, UVQK, 0, 0, 0, 0, 0, 0, 0);

        // rope + silu(v)-transpose, one launch
        ropevt_kernel<<<RV_GRID, 256>>>(uvqk, vth, qh, kh);

        // scores = q @ k^T  per batch (256 x 256 x 128)
        mma_gemm<0><<<dim3(LTOK / 128, LTOK / 128, NB), 256, GSMEM_SZ>>>(
            qh, kh,
            attnf, nullptr, nullptr,
            KDIM, KDIM, KDIM, LTOK, 0, 0,
            (long)LTOK * KDIM, (long)LTOK * KDIM, (long)LTOK * LTOK, 0, 0);

        softmax_kernel<<<ROWS, 256>>>(attnf, ath);

        // o = silu(u) * (attn @ v)   per batch (256 x 1536 x 256), fused epilogue
        mma_gemm<1><<<dim3(ED / 128, LTOK / 128, NB), 256, GSMEM_SZ>>>(
            ath, vth,
            nullptr, uvqk, oh,
            LTOK, LTOK, LTOK, 0, UVQK, ED,
            (long)LTOK * LTOK, (long)ED * LTOK, 0, (long)LTOK * UVQK, (long)LTOK * ED);

        // h += o @ Wout[l]   (4096 x 768 x 1536), fused residual
        mma_gemm<2><<<dim3(HD / 128, ROWS / 128, 1), 256, GSMEM_SZ>>>(
            oh, woh + (size_t)l * HD * ED,
            h, nullptr, nullptr,
            ED, ED, ED, HD, 0, 0, 0, 0, 0, 0, 0);
    }

    rmsnorm_kernel<<<ROWS, 256>>>(h, fnorm_w, xn, xnh);
    unpatch_kernel<<<ROWS, 256>>>(unpatchW, out);
}

// round 11
// speedup vs baseline: 3.9599x; 1.1418x over previous
#include <cuda_runtime.h>
#include <cuda_fp16.h>
#include <cstdint>
#include <cstddef>

// ---------------------------------------------------------------------------
// GAU denoising model. fp16 HMMA (mma.sync) GEMMs, fp32 elsewhere.
// Round 11: gemm0 epilogue fuses silu+fp16 (u), silu+transpose (v -> vth via
// smem), and compact qk extraction. vt kernel gone; gemm1 epilogue is a plain
// fp16 multiply; rope reads compact qk and folds in the 1/sqrt(K) scale.
// B=16, L=256 tokens, PD=192, H=768, E=1536, K=128, NL=24, rows=4096.
// ---------------------------------------------------------------------------

#define NB      16
#define LTOK    256
#define HD      768
#define ED      1536
#define KDIM    128
#define UVQK    3328
#define ROWS    4096
#define NLAYERS 24
#define PDIM    192

// ----- scratch (device globals; allocation is forbidden) --------------------
__device__ float g_h   [(size_t)ROWS * HD];
__device__ float g_xn  [(size_t)ROWS * HD];
__device__ __half g_xnh[(size_t)ROWS * HD];
__device__ __half g_uh [(size_t)ROWS * ED];        // silu(u), fp16
__device__ float g_qk  [(size_t)ROWS * 256];       // raw q|k (pre-rope)
__device__ __half g_qh [(size_t)ROWS * KDIM];      // rope'd q * scale, fp16
__device__ __half g_kh [(size_t)ROWS * KDIM];      // rope'd k, fp16
__device__ float g_attnf[(size_t)ROWS * LTOK];     // raw qk^T scores
__device__ __half g_attnh[(size_t)ROWS * LTOK];    // softmax probs
__device__ __half g_vth[(size_t)NB * ED * LTOK];   // silu(v)^T per batch [E][L]
__device__ __half g_oh [(size_t)ROWS * ED];        // silu(u)*av
__device__ __half g_wuvh[(size_t)NLAYERS * UVQK * HD];   // Wuv^T [N][K]
__device__ __half g_woh [(size_t)NLAYERS * HD * ED];     // Wout^T [N][K]

// ---------------------------------------------------------------------------
// PTX helpers (sm_80-era; compile for base sm_100)
// ---------------------------------------------------------------------------
__device__ __forceinline__ uint32_t smem_u32(const void* p) {
    uint32_t a;
    asm("{ .reg .u64 t; cvta.to.shared.u64 t, %1; cvt.u32.u64 %0, t; }"
        : "=r"(a) : "l"(p));
    return a;
}
__device__ __forceinline__ void cp16(uint32_t dst, const void* src) {
    asm volatile("cp.async.cg.shared.global [%0], [%1], 16;"
                 :: "r"(dst), "l"(src) : "memory");
}
#define CP_COMMIT() asm volatile("cp.async.commit_group;" ::: "memory")
#define CP_WAIT(N)  asm volatile("cp.async.wait_group %0;" :: "n"(N) : "memory")

__device__ __forceinline__ void ldsm4(uint32_t* r, uint32_t addr) {
    asm volatile("ldmatrix.sync.aligned.m8n8.x4.shared.b16 {%0,%1,%2,%3}, [%4];"
                 : "=r"(r[0]), "=r"(r[1]), "=r"(r[2]), "=r"(r[3]) : "r"(addr));
}
__device__ __forceinline__ void mma16816(float* c, const uint32_t* a,
                                         uint32_t b0, uint32_t b1) {
    asm volatile(
        "mma.sync.aligned.m16n8k16.row.col.f32.f16.f16.f32 "
        "{%0,%1,%2,%3}, {%4,%5,%6,%7}, {%8,%9}, {%0,%1,%2,%3};"
        : "+f"(c[0]), "+f"(c[1]), "+f"(c[2]), "+f"(c[3])
        : "r"(a[0]), "r"(a[1]), "r"(a[2]), "r"(a[3]), "r"(b0), "r"(b1));
}

__device__ __forceinline__ float silu_f(float x) {
    return x / (1.f + expf(-x));
}

// ---------------------------------------------------------------------------
// fp16 GEMM via mma.sync. C[M,N] from A[M,K] (row-major) and B[N,K] (K-major).
// CTA tile 128x128, BK=64, 8 warps (2m x 4n), warp tile 64x32.
// Smem tile: 128 rows x 64 halves (128B/row), 8-way XOR swizzle on 16B chunks:
//   phys(r, c) = r*128 + ((c ^ (r&7)) << 4)
// 3-stage cp.async pipeline.
// EPI 0: C = D (fp32)
// EPI 1: O = Uh * D -> fp16          (Uh already silu'd, fp16)
// EPI 2: C += D (residual)
// EPI 3: uvqk dispatch (gemm0 only): bn0<ED -> silu->fp16 u; bn0<2ED ->
//        silu -> smem transpose -> vth; else fp32 -> QK compact.
// ---------------------------------------------------------------------------
#define TILE_B   16384                   // 128 rows x 128 B
#define O_A      0
#define O_B      (TILE_B)
#define STAGE_B  (2 * TILE_B)            // 32768 B
#define NSTAGE   3
#define GSMEM_SZ (NSTAGE * STAGE_B)      // 98304 B
#define VSTR     144                     // transpose stage stride (halves)

__device__ __forceinline__ uint32_t swz64(uint32_t r, uint32_t c) {
    return r * 128u + ((c ^ (r & 7u)) << 4);
}

template <int EPI>
__global__ void __launch_bounds__(256, 2) mma_gemm(
    const __half* __restrict__ A, const __half* __restrict__ B,
    float* __restrict__ C, const __half* __restrict__ Uh,
    __half* __restrict__ Oh, __half* __restrict__ Vt, float* __restrict__ QK,
    int K, int lda, int ldb, int ldc, int ldu, int ldo,
    long sA, long sB, long sC, long sU, long sO) {

    extern __shared__ char smem[];
    uint32_t sb = smem_u32(smem);
    int t = threadIdx.x, lane = t & 31, wid = t >> 5;
    int wm = (wid >> 2) * 64, wn = (wid & 3) * 32;
    int bn0 = blockIdx.x * 128, bm0 = blockIdx.y * 128;
    long z = blockIdx.z;
    A += z * sA; B += z * sB;
    if (EPI == 0 || EPI == 2) C += z * sC;
    if (EPI == 1) { Uh += z * sU; Oh += z * sO; }

    float acc[4][4][4] = {};            // [mtile][ntile][c0..c3]

    auto load_stage = [&](int buf, int kt) {
        uint32_t base = sb + buf * STAGE_B;
        #pragma unroll
        for (int i = 0; i < 4; i++) {
            int id = t + i * 256;
            uint32_t row = (uint32_t)(id >> 3), c = (uint32_t)(id & 7);
            uint32_t d = swz64(row, c);
            cp16(base + O_A + d, A + (size_t)(bm0 + row) * lda + kt + c * 8);
            cp16(base + O_B + d, B + (size_t)(bn0 + row) * ldb + kt + c * 8);
        }
        CP_COMMIT();
    };

    uint32_t aoff[4], boff[2];
    {
        uint32_t ac = (uint32_t)(lane >> 4);
        uint32_t ar = (uint32_t)(wm + (lane & 15));
        #pragma unroll
        for (int mt = 0; mt < 4; mt++) aoff[mt] = swz64(ar + mt * 16, ac);
        uint32_t bc = (uint32_t)((lane >> 3) & 1);
        uint32_t br = (uint32_t)(wn + ((lane >> 4) << 3) + (lane & 7));
        #pragma unroll
        for (int ntp = 0; ntp < 2; ntp++) boff[ntp] = swz64(br + ntp * 16, bc);
    }

    int nk = K / 64;
    load_stage(0, 0);
    if (nk > 1) load_stage(1, 64);
    else        CP_COMMIT();

    for (int s = 0; s < nk; s++) {
        CP_WAIT(1);
        __syncthreads();
        if (s + 2 < nk) load_stage((s + 2) % NSTAGE, (s + 2) * 64);
        else            CP_COMMIT();

        uint32_t base = sb + (s % NSTAGE) * STAGE_B;
        #pragma unroll
        for (int ks = 0; ks < 4; ks++) {
            uint32_t kx = (uint32_t)ks << 5;
            uint32_t bf[8], af[4][4];
            ldsm4(bf,     base + O_B + (boff[0] ^ kx));
            ldsm4(bf + 4, base + O_B + (boff[1] ^ kx));
            #pragma unroll
            for (int mt = 0; mt < 4; mt++)
                ldsm4(af[mt], base + O_A + (aoff[mt] ^ kx));
            #pragma unroll
            for (int mt = 0; mt < 4; mt++)
                #pragma unroll
                for (int nt = 0; nt < 4; nt++)
                    mma16816(acc[mt][nt], af[mt], bf[nt * 2], bf[nt * 2 + 1]);
        }
    }

    // -------- epilogue ------------------------------------------------------
    int g = lane >> 2, tc = lane & 3;

    if (EPI == 3 && bn0 >= ED && bn0 < 2 * ED) {
        // v region: silu -> smem transpose -> coalesced vth writes.
        __syncthreads();                 // all warps done reading smem stages
        __half* vs = (__half*)smem;      // [128 n][VSTR] halves
        int b = bm0 >> 8, l0 = bm0 & 255, gn0 = bn0 - ED;
        #pragma unroll
        for (int mt = 0; mt < 4; mt++) {
            #pragma unroll
            for (int nt = 0; nt < 4; nt++) {
                float* c = acc[mt][nt];
                int nn = wn + nt * 8 + tc * 2;
                #pragma unroll
                for (int half = 0; half < 2; half++) {
                    int l = wm + mt * 16 + g + half * 8;
                    vs[nn * VSTR + l]       = __float2half(silu_f(c[half * 2]));
                    vs[(nn + 1) * VSTR + l] = __float2half(silu_f(c[half * 2 + 1]));
                }
            }
        }
        __syncthreads();
        for (int i = t; i < 128 * 16; i += 256) {
            int n = i >> 4, sg = i & 15;
            uint4 val = *(const uint4*)(vs + n * VSTR + sg * 8);
            *(uint4*)(Vt + ((size_t)b * ED + gn0 + n) * LTOK + l0 + sg * 8) = val;
        }
        return;
    }

    #pragma unroll
    for (int mt = 0; mt < 4; mt++) {
        #pragma unroll
        for (int nt = 0; nt < 4; nt++) {
            float* c = acc[mt][nt];
            int r0 = bm0 + wm + mt * 16 + g;
            int c0 = bn0 + wn + nt * 8 + tc * 2;
            #pragma unroll
            for (int half = 0; half < 2; half++) {
                int r = r0 + half * 8;
                float v0 = c[half * 2], v1 = c[half * 2 + 1];
                if (EPI == 0) {
                    float2 st = {v0, v1};
                    *(float2*)&C[(size_t)r * ldc + c0] = st;
                } else if (EPI == 1) {
                    __half2 uv = *(const __half2*)&Uh[(size_t)r * ldu + c0];
                    __half2 hp;
                    hp.x = __float2half(__half2float(uv.x) * v0);
                    hp.y = __float2half(__half2float(uv.y) * v1);
                    *(__half2*)&Oh[(size_t)r * ldo + c0] = hp;
                } else if (EPI == 2) {
                    float2* p = (float2*)&C[(size_t)r * ldc + c0];
                    float2 old = *p;
                    old.x += v0; old.y += v1;
                    *p = old;
                } else {  // EPI == 3, u or qk region
                    if (bn0 < ED) {
                        __half2 hp;
                        hp.x = __float2half(silu_f(v0));
                        hp.y = __float2half(silu_f(v1));
                        *(__half2*)&Oh[(size_t)r * ED + c0] = hp;
                    } else {
                        float2 st = {v0, v1};
                        *(float2*)&QK[(size_t)r * 256 + (c0 - 2 * ED)] = st;
                    }
                }
            }
        }
    }
}

// ---------------------------------------------------------------------------
// Merged weight transpose + fp16 convert (one launch; keeps gemm0 at idx 3).
// ---------------------------------------------------------------------------
#define NT1 ((UVQK / 32) * (HD / 32))
#define NT2 ((HD / 32) * (ED / 32))
#define WCONV_GRID (NLAYERS * (NT1 + NT2))

__global__ void wconv_kernel(const float* __restrict__ Wuv,
                             const float* __restrict__ Wout,
                             __half* __restrict__ wuvh,
                             __half* __restrict__ woh) {
    int idx = blockIdx.x;
    int layer = idx / (NT1 + NT2);
    int r = idx % (NT1 + NT2);
    const float* in; __half* oh; int K, N, nb, kb;
    if (r < NT1) {
        K = HD; N = UVQK; nb = r % (UVQK / 32); kb = r / (UVQK / 32);
        in = Wuv + (size_t)layer * HD * UVQK;
        oh = wuvh + (size_t)layer * HD * UVQK;
    } else {
        r -= NT1;
        K = ED; N = HD; nb = r % (HD / 32); kb = r / (HD / 32);
        in = Wout + (size_t)layer * ED * HD;
        oh = woh + (size_t)layer * ED * HD;
    }
    __shared__ float tile[32][33];
    int n0 = nb * 32, k0 = kb * 32;
    int tx = threadIdx.x & 31, ty = threadIdx.x >> 5;
    #pragma unroll
    for (int i = 0; i < 4; i++)
        tile[ty + i * 8][tx] = in[(size_t)(k0 + ty + i * 8) * N + n0 + tx];
    __syncthreads();
    #pragma unroll
    for (int i = 0; i < 4; i++) {
        int n = n0 + ty + i * 8, k = k0 + tx;
        oh[(size_t)n * K + k] = __float2half(tile[tx][ty + i * 8]);
    }
}

// ---------------------------------------------------------------------------
// Patchify + patch_W GEMM + time-embedding bias (validated round 1).
// ---------------------------------------------------------------------------
__global__ void patch_kernel(const float* __restrict__ x,
                             const int*   __restrict__ t_idx,
                             const float* __restrict__ pw,
                             const float* __restrict__ temb) {
    int r = blockIdx.x;
    int b = r >> 8, l = r & 255;
    int gy = l >> 4, gx = l & 15;
    int t = threadIdx.x;
    __shared__ float xr[PDIM];
    if (t < PDIM) {
        int py = t / 24, rem = t % 24, px = rem / 3, c = rem % 3;
        xr[t] = x[(((size_t)(b * 3 + c) * 128) + (gy * 8 + py)) * 128 + gx * 8 + px];
    }
    __syncthreads();
    const float* bias = temb + (size_t)t_idx[b] * HD;
    for (int col = t; col < HD; col += 256) {
        float s = 0.f;
        #pragma unroll 4
        for (int k = 0; k < PDIM; k++) s += xr[k] * pw[(size_t)k * HD + col];
        g_h[(size_t)r * HD + col] = s + bias[col];
    }
}

// ---------------------------------------------------------------------------
// RMSNorm: fp16 out always; fp32 out only when outp != nullptr.
// ---------------------------------------------------------------------------
__global__ void rmsnorm_kernel(const float* __restrict__ in,
                               const float* __restrict__ w,
                               float* __restrict__ outp,
                               __half* __restrict__ oh) {
    int r = blockIdx.x, t = threadIdx.x;
    int lane = t & 31, wid = t >> 5;
    const float* row = in + (size_t)r * HD;
    float v0 = row[t], v1 = row[t + 256], v2 = row[t + 512];
    float ss = v0 * v0 + v1 * v1 + v2 * v2;
    #pragma unroll
    for (int o = 16; o > 0; o >>= 1) ss += __shfl_xor_sync(0xffffffffu, ss, o);
    __shared__ float wred[8];
    if (lane == 0) wred[wid] = ss;
    __syncthreads();
    float tot = wred[0];
    #pragma unroll
    for (int i = 1; i < 8; i++) tot += wred[i];
    float inv = 1.f / (sqrtf(tot * (1.0f / HD)) + 1e-6f);
    size_t base = (size_t)r * HD;
    #pragma unroll
    for (int i = 0; i < 3; i++) {
        int c = t + i * 256;
        float v = (i == 0 ? v0 : i == 1 ? v1 : v2) * inv * w[c];
        if (outp) outp[base + c] = v;
        oh[base + c] = __float2half(v);
    }
}

// ---------------------------------------------------------------------------
// RoPE from compact qk buffer; folds 1/sqrt(K) into q. 4 rows per block.
// ---------------------------------------------------------------------------
__global__ void rope_kernel(const float* __restrict__ qk,
                            __half* __restrict__ qh,
                            __half* __restrict__ kh) {
    int t = threadIdx.x;
    int r = blockIdx.x * 4 + (t >> 6);
    int j = t & 63;
    const float* row = qk + (size_t)r * 256;
    int l = r & 255;
    float p1 = (float)(l >> 4), p2 = (float)(l & 15);
    int jj = (j < 32) ? j : j - 32;
    float f  = expf(-6.907755278982137f * (float)jj * (1.0f / 31.0f));
    float a1 = p1 * f, a2 = p2 * f;
    float sv = (j < 32) ? sinf(a1) : cosf(a1);
    float cv = (j < 32) ? sinf(a2) : cosf(a2);
    const float SC = 0.08838834764831845f;
    float q1 = row[j], q2 = row[j + 64];
    qh[(size_t)r * KDIM + j]      = __float2half((q1 * cv - q2 * sv) * SC);
    qh[(size_t)r * KDIM + j + 64] = __float2half((q2 * cv + q1 * sv) * SC);
    float k1 = row[128 + j], k2 = row[192 + j];
    kh[(size_t)r * KDIM + j]      = __float2half(k1 * cv - k2 * sv);
    kh[(size_t)r * KDIM + j + 64] = __float2half(k2 * cv + k1 * sv);
}

// ---------------------------------------------------------------------------
// Softmax over raw scores (scale already folded into q). Shuffle reduction.
// ---------------------------------------------------------------------------
__global__ void softmax_kernel(const float* __restrict__ sc,
                               __half* __restrict__ ah) {
    int r = blockIdx.x, t = threadIdx.x;
    int lane = t & 31, wid = t >> 5;
    __shared__ float wmax[8], wsum[8];
    float s = sc[(size_t)r * 256 + t];
    float m = s;
    #pragma unroll
    for (int o = 16; o > 0; o >>= 1) m = fmaxf(m, __shfl_xor_sync(0xffffffffu, m, o));
    if (lane == 0) wmax[wid] = m;
    __syncthreads();
    float mx = wmax[0];
    #pragma unroll
    for (int i = 1; i < 8; i++) mx = fmaxf(mx, wmax[i]);
    float e = expf(s - mx);
    float su = e;
    #pragma unroll
    for (int o = 16; o > 0; o >>= 1) su += __shfl_xor_sync(0xffffffffu, su, o);
    if (lane == 0) wsum[wid] = su;
    __syncthreads();
    float tot = wsum[0];
    #pragma unroll
    for (int i = 1; i < 8; i++) tot += wsum[i];
    ah[(size_t)r * 256 + t] = __float2half(e / tot);
}

// ---------------------------------------------------------------------------
// Final unpatch (validated round 1).
// ---------------------------------------------------------------------------
__global__ void unpatch_kernel(const float* __restrict__ uw, float* __restrict__ out) {
    int r = blockIdx.x, t = threadIdx.x;
    int b = r >> 8, l = r & 255, gy = l >> 4, gx = l & 15;
    __shared__ float xr[HD];
    const float* row = g_xn + (size_t)r * HD;
    xr[t] = row[t]; xr[t + 256] = row[t + 256]; xr[t + 512] = row[t + 512];
    __syncthreads();
    if (t < PDIM) {
        float s = 0.f;
        #pragma unroll 4
        for (int k = 0; k < HD; k++) s += xr[k] * uw[(size_t)k * PDIM + t];
        int py = t / 24, rem = t % 24, px = rem / 3, c = rem % 3;
        out[(((size_t)(b * 3 + c) * 128) + (gy * 8 + py)) * 128 + gx * 8 + px] = s;
    }
}

// ---------------------------------------------------------------------------
// Host launcher
// ---------------------------------------------------------------------------
extern "C" void kernel_launch(void* const* d_in, const int* in_sizes, int n_in,
                              void* d_out, int out_size) {
    const float* x        = (const float*)d_in[0];
    const int*   t_idx    = (const int*)  d_in[1];
    const float* patch_W  = (const float*)d_in[2];
    const float* t_emb    = (const float*)d_in[3];
    const float* Wuv      = (const float*)d_in[4];
    const float* Wout     = (const float*)d_in[5];
    const float* gnorm    = (const float*)d_in[6];
    const float* fnorm_w  = (const float*)d_in[7];
    const float* unpatchW = (const float*)d_in[8];
    float* out = (float*)d_out;

    float *h, *xn, *qk, *attnf;
    __half *xnh, *uh, *qh, *kh, *ath, *vth, *oh, *wuvh, *woh;
    cudaGetSymbolAddress((void**)&h,     g_h);
    cudaGetSymbolAddress((void**)&xn,    g_xn);
    cudaGetSymbolAddress((void**)&xnh,   g_xnh);
    cudaGetSymbolAddress((void**)&uh,    g_uh);
    cudaGetSymbolAddress((void**)&qk,    g_qk);
    cudaGetSymbolAddress((void**)&qh,    g_qh);
    cudaGetSymbolAddress((void**)&kh,    g_kh);
    cudaGetSymbolAddress((void**)&attnf, g_attnf);
    cudaGetSymbolAddress((void**)&ath,   g_attnh);
    cudaGetSymbolAddress((void**)&vth,   g_vth);
    cudaGetSymbolAddress((void**)&oh,    g_oh);
    cudaGetSymbolAddress((void**)&wuvh,  g_wuvh);
    cudaGetSymbolAddress((void**)&woh,   g_woh);

    cudaFuncSetAttribute(mma_gemm<0>, cudaFuncAttributeMaxDynamicSharedMemorySize, GSMEM_SZ);
    cudaFuncSetAttribute(mma_gemm<1>, cudaFuncAttributeMaxDynamicSharedMemorySize, GSMEM_SZ);
    cudaFuncSetAttribute(mma_gemm<2>, cudaFuncAttributeMaxDynamicSharedMemorySize, GSMEM_SZ);
    cudaFuncSetAttribute(mma_gemm<3>, cudaFuncAttributeMaxDynamicSharedMemorySize, GSMEM_SZ);

    // launch 0: merged weight transpose + fp16 convert
    wconv_kernel<<<WCONV_GRID, 256>>>(Wuv, Wout, wuvh, woh);

    // launch 1
    patch_kernel<<<ROWS, 256>>>(x, t_idx, patch_W, t_emb);

    for (int l = 0; l < NLAYERS; l++) {
        // launch 2 (first iter); fp32 out skipped during layers
        rmsnorm_kernel<<<ROWS, 256>>>(h, gnorm + (size_t)l * HD, nullptr, xnh);

        // launch 3 (first iter) -> ncu-captured: fused uvqk GEMM + epilogues
        mma_gemm<3><<<dim3(UVQK / 128, ROWS / 128, 1), 256, GSMEM_SZ>>>(
            xnh, wuvh + (size_t)l * UVQK * HD,
            nullptr, nullptr, uh, vth, qk,
            HD, HD, HD, 0, 0, 0,
            0, 0, 0, 0, 0);

        rope_kernel<<<ROWS / 4, 256>>>(qk, qh, kh);

        // scores = q @ k^T  per batch (256 x 256 x 128)
        mma_gemm<0><<<dim3(LTOK / 128, LTOK / 128, NB), 256, GSMEM_SZ>>>(
            qh, kh, attnf, nullptr, nullptr, nullptr, nullptr,
            KDIM, KDIM, KDIM, LTOK, 0, 0,
            (long)LTOK * KDIM, (long)LTOK * KDIM, (long)LTOK * LTOK, 0, 0);

        softmax_kernel<<<ROWS, 256>>>(attnf, ath);

        // o = uh * (attn @ v)   per batch (256 x 1536 x 256)
        mma_gemm<1><<<dim3(ED / 128, LTOK / 128, NB), 256, GSMEM_SZ>>>(
            ath, vth, nullptr, uh, oh, nullptr, nullptr,
            LTOK, LTOK, LTOK, 0, ED, ED,
            (long)LTOK * LTOK, (long)ED * LTOK, 0,
            (long)LTOK * ED, (long)LTOK * ED);

        // h += o @ Wout[l]   (4096 x 768 x 1536), fused residual
        mma_gemm<2><<<dim3(HD / 128, ROWS / 128, 1), 256, GSMEM_SZ>>>(
            oh, woh + (size_t)l * HD * ED,
            h, nullptr, nullptr, nullptr, nullptr,
            ED, ED, ED, HD, 0, 0,
            0, 0, 0, 0, 0);
    }

    rmsnorm_kernel<<<ROWS, 256>>>(h, fnorm_w, xn, xnh);
    unpatch_kernel<<<ROWS, 256>>>(unpatchW, out);
}

// round 12
// speedup vs baseline: 4.1523x; 1.0486x over previous
#include <cuda_runtime.h>
#include <cuda_fp16.h>
#include <cstdint>
#include <cstddef>

// ---------------------------------------------------------------------------
// GAU denoising model. fp16 HMMA (mma.sync) GEMMs, fp32 elsewhere.
// Round 12: rope folded into gemm3's qk epilogue (q/k tiles are pure blocks);
// scores+softmax fused into one full-row-per-warp attention kernel.
// Per-layer launches: rmsnorm, gemm3, attn_fused, gemm1, gemm2.
// B=16, L=256 tokens, PD=192, H=768, E=1536, K=128, NL=24, rows=4096.
// ---------------------------------------------------------------------------

#define NB      16
#define LTOK    256
#define HD      768
#define ED      1536
#define KDIM    128
#define UVQK    3328
#define ROWS    4096
#define NLAYERS 24
#define PDIM    192

// ----- scratch (device globals; allocation is forbidden) --------------------
__device__ float g_h   [(size_t)ROWS * HD];
__device__ float g_xn  [(size_t)ROWS * HD];
__device__ __half g_xnh[(size_t)ROWS * HD];
__device__ __half g_uh [(size_t)ROWS * ED];        // silu(u), fp16
__device__ __half g_qh [(size_t)ROWS * KDIM];      // rope'd q * scale, fp16
__device__ __half g_kh [(size_t)ROWS * KDIM];      // rope'd k, fp16
__device__ __half g_attnh[(size_t)ROWS * LTOK];    // softmax probs
__device__ __half g_vth[(size_t)NB * ED * LTOK];   // silu(v)^T per batch [E][L]
__device__ __half g_oh [(size_t)ROWS * ED];        // silu(u)*av
__device__ __half g_wuvh[(size_t)NLAYERS * UVQK * HD];   // Wuv^T [N][K]
__device__ __half g_woh [(size_t)NLAYERS * HD * ED];     // Wout^T [N][K]

// ---------------------------------------------------------------------------
// PTX helpers (sm_80-era; compile for base sm_100)
// ---------------------------------------------------------------------------
__device__ __forceinline__ uint32_t smem_u32(const void* p) {
    uint32_t a;
    asm("{ .reg .u64 t; cvta.to.shared.u64 t, %1; cvt.u32.u64 %0, t; }"
        : "=r"(a) : "l"(p));
    return a;
}
__device__ __forceinline__ void cp16(uint32_t dst, const void* src) {
    asm volatile("cp.async.cg.shared.global [%0], [%1], 16;"
                 :: "r"(dst), "l"(src) : "memory");
}
#define CP_COMMIT() asm volatile("cp.async.commit_group;" ::: "memory")
#define CP_WAIT(N)  asm volatile("cp.async.wait_group %0;" :: "n"(N) : "memory")

__device__ __forceinline__ void ldsm4(uint32_t* r, uint32_t addr) {
    asm volatile("ldmatrix.sync.aligned.m8n8.x4.shared.b16 {%0,%1,%2,%3}, [%4];"
                 : "=r"(r[0]), "=r"(r[1]), "=r"(r[2]), "=r"(r[3]) : "r"(addr));
}
__device__ __forceinline__ void mma16816(float* c, const uint32_t* a,
                                         uint32_t b0, uint32_t b1) {
    asm volatile(
        "mma.sync.aligned.m16n8k16.row.col.f32.f16.f16.f32 "
        "{%0,%1,%2,%3}, {%4,%5,%6,%7}, {%8,%9}, {%0,%1,%2,%3};"
        : "+f"(c[0]), "+f"(c[1]), "+f"(c[2]), "+f"(c[3])
        : "r"(a[0]), "r"(a[1]), "r"(a[2]), "r"(a[3]), "r"(b0), "r"(b1));
}

__device__ __forceinline__ float silu_f(float x) {
    return x / (1.f + expf(-x));
}

#define TILE_B   16384                   // 128 rows x 128 B
#define O_A      0
#define O_B      (TILE_B)
#define STAGE_B  (2 * TILE_B)            // 32768 B
#define NSTAGE   3
#define GSMEM_SZ (NSTAGE * STAGE_B)      // 98304 B
#define VSTR     144                     // v transpose stage stride (halves)
#define QSTR     132                     // qk rope stage stride (floats)

__device__ __forceinline__ uint32_t swz64(uint32_t r, uint32_t c) {
    return r * 128u + ((c ^ (r & 7u)) << 4);
}

// ---------------------------------------------------------------------------
// fp16 GEMM via mma.sync. C[M,N] from A[M,K] (row-major) and B[N,K] (K-major).
// CTA tile 128x128, BK=64, 8 warps (2m x 4n), warp tile 64x32.
// EPI 1: O = Uh * D -> fp16          (Uh already silu'd, fp16)
// EPI 2: C += D (residual)
// EPI 3: uvqk dispatch (gemm0 only): bn0<ED -> silu->fp16 u; bn0<2ED ->
//        silu -> smem transpose -> vth; else fp32 -> smem -> rope -> qh/kh.
// ---------------------------------------------------------------------------
template <int EPI>
__global__ void __launch_bounds__(256, 2) mma_gemm(
    const __half* __restrict__ A, const __half* __restrict__ B,
    float* __restrict__ C, const __half* __restrict__ Uh,
    __half* __restrict__ Oh, __half* __restrict__ Vt,
    __half* __restrict__ Qr, __half* __restrict__ Kr,
    int K, int lda, int ldb, int ldc, int ldu, int ldo,
    long sA, long sB, long sC, long sU, long sO) {

    extern __shared__ char smem[];
    uint32_t sb = smem_u32(smem);
    int t = threadIdx.x, lane = t & 31, wid = t >> 5;
    int wm = (wid >> 2) * 64, wn = (wid & 3) * 32;
    int bn0 = blockIdx.x * 128, bm0 = blockIdx.y * 128;
    long z = blockIdx.z;
    A += z * sA; B += z * sB;
    if (EPI == 2) C += z * sC;
    if (EPI == 1) { Uh += z * sU; Oh += z * sO; }

    float acc[4][4][4] = {};            // [mtile][ntile][c0..c3]

    auto load_stage = [&](int buf, int kt) {
        uint32_t base = sb + buf * STAGE_B;
        #pragma unroll
        for (int i = 0; i < 4; i++) {
            int id = t + i * 256;
            uint32_t row = (uint32_t)(id >> 3), c = (uint32_t)(id & 7);
            uint32_t d = swz64(row, c);
            cp16(base + O_A + d, A + (size_t)(bm0 + row) * lda + kt + c * 8);
            cp16(base + O_B + d, B + (size_t)(bn0 + row) * ldb + kt + c * 8);
        }
        CP_COMMIT();
    };

    uint32_t aoff[4], boff[2];
    {
        uint32_t ac = (uint32_t)(lane >> 4);
        uint32_t ar = (uint32_t)(wm + (lane & 15));
        #pragma unroll
        for (int mt = 0; mt < 4; mt++) aoff[mt] = swz64(ar + mt * 16, ac);
        uint32_t bc = (uint32_t)((lane >> 3) & 1);
        uint32_t br = (uint32_t)(wn + ((lane >> 4) << 3) + (lane & 7));
        #pragma unroll
        for (int ntp = 0; ntp < 2; ntp++) boff[ntp] = swz64(br + ntp * 16, bc);
    }

    int nk = K / 64;
    load_stage(0, 0);
    if (nk > 1) load_stage(1, 64);
    else        CP_COMMIT();

    for (int s = 0; s < nk; s++) {
        CP_WAIT(1);
        __syncthreads();
        if (s + 2 < nk) load_stage((s + 2) % NSTAGE, (s + 2) * 64);
        else            CP_COMMIT();

        uint32_t base = sb + (s % NSTAGE) * STAGE_B;
        #pragma unroll
        for (int ks = 0; ks < 4; ks++) {
            uint32_t kx = (uint32_t)ks << 5;
            uint32_t bf[8], af[4][4];
            ldsm4(bf,     base + O_B + (boff[0] ^ kx));
            ldsm4(bf + 4, base + O_B + (boff[1] ^ kx));
            #pragma unroll
            for (int mt = 0; mt < 4; mt++)
                ldsm4(af[mt], base + O_A + (aoff[mt] ^ kx));
            #pragma unroll
            for (int mt = 0; mt < 4; mt++)
                #pragma unroll
                for (int nt = 0; nt < 4; nt++)
                    mma16816(acc[mt][nt], af[mt], bf[nt * 2], bf[nt * 2 + 1]);
        }
    }

    // -------- epilogue ------------------------------------------------------
    int g = lane >> 2, tc = lane & 3;

    if (EPI == 3 && bn0 >= ED && bn0 < 2 * ED) {
        // v region: silu -> smem transpose -> coalesced vth writes.
        __syncthreads();
        __half* vs = (__half*)smem;      // [128 n][VSTR] halves
        int b = bm0 >> 8, l0 = bm0 & 255, gn0 = bn0 - ED;
        #pragma unroll
        for (int mt = 0; mt < 4; mt++) {
            #pragma unroll
            for (int nt = 0; nt < 4; nt++) {
                float* c = acc[mt][nt];
                int nn = wn + nt * 8 + tc * 2;
                #pragma unroll
                for (int half = 0; half < 2; half++) {
                    int l = wm + mt * 16 + g + half * 8;
                    vs[nn * VSTR + l]       = __float2half(silu_f(c[half * 2]));
                    vs[(nn + 1) * VSTR + l] = __float2half(silu_f(c[half * 2 + 1]));
                }
            }
        }
        __syncthreads();
        for (int i = t; i < 128 * 16; i += 256) {
            int n = i >> 4, sg = i & 15;
            uint4 val = *(const uint4*)(vs + n * VSTR + sg * 8);
            *(uint4*)(Vt + ((size_t)b * ED + gn0 + n) * LTOK + l0 + sg * 8) = val;
        }
        return;
    }

    if (EPI == 3 && bn0 >= 2 * ED) {
        // q or k region (pure 128-wide blocks): stage fp32 -> rope -> fp16.
        __syncthreads();
        float* qs = (float*)smem;        // [128 rows][QSTR]
        #pragma unroll
        for (int mt = 0; mt < 4; mt++) {
            #pragma unroll
            for (int nt = 0; nt < 4; nt++) {
                float* c = acc[mt][nt];
                int col = wn + nt * 8 + tc * 2;
                #pragma unroll
                for (int half = 0; half < 2; half++) {
                    int row = wm + mt * 16 + g + half * 8;
                    qs[row * QSTR + col]     = c[half * 2];
                    qs[row * QSTR + col + 1] = c[half * 2 + 1];
                }
            }
        }
        __syncthreads();
        bool isq = (bn0 == 2 * ED);
        const float SC = 0.08838834764831845f;
        for (int i = t; i < 128 * 64; i += 256) {
            int row = i >> 6, j = i & 63;
            int gr = bm0 + row;
            int l = gr & 255;
            float p1 = (float)(l >> 4), p2 = (float)(l & 15);
            int jj = (j < 32) ? j : j - 32;
            float f  = expf(-6.907755278982137f * (float)jj * (1.0f / 31.0f));
            float a1 = p1 * f, a2 = p2 * f;
            float sv = (j < 32) ? sinf(a1) : cosf(a1);
            float cv = (j < 32) ? sinf(a2) : cosf(a2);
            float v1 = qs[row * QSTR + j], v2 = qs[row * QSTR + j + 64];
            float o1 = v1 * cv - v2 * sv;
            float o2 = v2 * cv + v1 * sv;
            if (isq) {
                Qr[(size_t)gr * KDIM + j]      = __float2half(o1 * SC);
                Qr[(size_t)gr * KDIM + j + 64] = __float2half(o2 * SC);
            } else {
                Kr[(size_t)gr * KDIM + j]      = __float2half(o1);
                Kr[(size_t)gr * KDIM + j + 64] = __float2half(o2);
            }
        }
        return;
    }

    #pragma unroll
    for (int mt = 0; mt < 4; mt++) {
        #pragma unroll
        for (int nt = 0; nt < 4; nt++) {
            float* c = acc[mt][nt];
            int r0 = bm0 + wm + mt * 16 + g;
            int c0 = bn0 + wn + nt * 8 + tc * 2;
            #pragma unroll
            for (int half = 0; half < 2; half++) {
                int r = r0 + half * 8;
                float v0 = c[half * 2], v1 = c[half * 2 + 1];
                if (EPI == 1) {
                    __half2 uv = *(const __half2*)&Uh[(size_t)r * ldu + c0];
                    __half2 hp;
                    hp.x = __float2half(__half2float(uv.x) * v0);
                    hp.y = __float2half(__half2float(uv.y) * v1);
                    *(__half2*)&Oh[(size_t)r * ldo + c0] = hp;
                } else if (EPI == 2) {
                    float2* p = (float2*)&C[(size_t)r * ldc + c0];
                    float2 old = *p;
                    old.x += v0; old.y += v1;
                    *p = old;
                } else {  // EPI == 3, u region
                    __half2 hp;
                    hp.x = __float2half(silu_f(v0));
                    hp.y = __float2half(silu_f(v1));
                    *(__half2*)&Oh[(size_t)r * ED + c0] = hp;
                }
            }
        }
    }
}

// ---------------------------------------------------------------------------
// Fused scores + softmax. CTA = 32 q-rows x one batch (grid 8 x 16).
// 8 warps, each spans the FULL 256-wide row (warp tile 32x32, wn = wid*32),
// so row softmax = tc-shuffle + one 32x8 smem reduction per pass.
// smem: Qlo|Qhi (4KB each) | Klo|Khi (32KB each) | red | red2.
// ---------------------------------------------------------------------------
#define AT_Q    0
#define AT_K    8192
#define AT_RED  73728
#define AT_SMEM 75776

__global__ void __launch_bounds__(256, 2) attn_fused(
    const __half* __restrict__ qh, const __half* __restrict__ kh,
    __half* __restrict__ ah) {
    extern __shared__ char smem[];
    uint32_t sb = smem_u32(smem);
    int t = threadIdx.x, lane = t & 31, wid = t >> 5;
    int m0 = blockIdx.x * 32;
    int z  = blockIdx.y;
    const __half* Q  = qh + ((size_t)z * 256 + m0) * KDIM;
    const __half* Kp = kh + (size_t)z * 256 * KDIM;

    // Load Q (32 rows) and K (256 rows), kdim split into two 64-half tiles.
    #pragma unroll
    for (int i = t; i < 512; i += 256) {
        int h = i >> 8, id = i & 255;
        uint32_t row = (uint32_t)(id >> 3), c = (uint32_t)(id & 7);
        cp16(sb + AT_Q + h * 4096 + swz64(row, c),
             Q + (size_t)row * KDIM + h * 64 + c * 8);
    }
    #pragma unroll
    for (int i = t; i < 4096; i += 256) {
        int h = i >> 11, id = i & 2047;
        uint32_t row = (uint32_t)(id >> 3), c = (uint32_t)(id & 7);
        cp16(sb + AT_K + h * 32768 + swz64(row, c),
             Kp + (size_t)row * KDIM + h * 64 + c * 8);
    }
    CP_COMMIT();
    CP_WAIT(0);
    __syncthreads();

    float acc[2][4][4] = {};
    int wn = wid * 32;
    uint32_t aoff[2], boff[2];
    {
        uint32_t ac = (uint32_t)(lane >> 4);
        uint32_t ar = (uint32_t)(lane & 15);
        aoff[0] = swz64(ar, ac);
        aoff[1] = swz64(ar + 16, ac);
        uint32_t bc = (uint32_t)((lane >> 3) & 1);
        uint32_t br = (uint32_t)(wn + ((lane >> 4) << 3) + (lane & 7));
        boff[0] = swz64(br, bc);
        boff[1] = swz64(br + 16, bc);
    }

    #pragma unroll
    for (int h = 0; h < 2; h++) {
        uint32_t qb = sb + AT_Q + h * 4096;
        uint32_t kb = sb + AT_K + h * 32768;
        #pragma unroll
        for (int ks = 0; ks < 4; ks++) {
            uint32_t kx = (uint32_t)ks << 5;
            uint32_t bf[8], af[2][4];
            ldsm4(bf,     kb + (boff[0] ^ kx));
            ldsm4(bf + 4, kb + (boff[1] ^ kx));
            ldsm4(af[0],  qb + (aoff[0] ^ kx));
            ldsm4(af[1],  qb + (aoff[1] ^ kx));
            #pragma unroll
            for (int mt = 0; mt < 2; mt++)
                #pragma unroll
                for (int nt = 0; nt < 4; nt++)
                    mma16816(acc[mt][nt], af[mt], bf[nt * 2], bf[nt * 2 + 1]);
        }
    }

    // Softmax: rows = mt*16 + g + half*8 (4 per thread), cols = full 256.
    float* red  = (float*)(smem + AT_RED);      // [32][8]
    float* red2 = red + 256;                     // [32][8]
    int g = lane >> 2, tc = lane & 3;

    // pass 1: row max
    #pragma unroll
    for (int mt = 0; mt < 2; mt++) {
        #pragma unroll
        for (int half = 0; half < 2; half++) {
            float m = acc[mt][0][half * 2];
            #pragma unroll
            for (int nt = 0; nt < 4; nt++) {
                m = fmaxf(m, acc[mt][nt][half * 2]);
                m = fmaxf(m, acc[mt][nt][half * 2 + 1]);
            }
            m = fmaxf(m, __shfl_xor_sync(0xffffffffu, m, 1));
            m = fmaxf(m, __shfl_xor_sync(0xffffffffu, m, 2));
            if (tc == 0) red[(mt * 16 + g + half * 8) * 8 + wid] = m;
        }
    }
    __syncthreads();
    // pass 2: exp + row sum
    #pragma unroll
    for (int mt = 0; mt < 2; mt++) {
        #pragma unroll
        for (int half = 0; half < 2; half++) {
            int row = mt * 16 + g + half * 8;
            float mx = red[row * 8];
            #pragma unroll
            for (int w = 1; w < 8; w++) mx = fmaxf(mx, red[row * 8 + w]);
            float su = 0.f;
            #pragma unroll
            for (int nt = 0; nt < 4; nt++) {
                float e0 = expf(acc[mt][nt][half * 2]     - mx);
                float e1 = expf(acc[mt][nt][half * 2 + 1] - mx);
                acc[mt][nt][half * 2]     = e0;
                acc[mt][nt][half * 2 + 1] = e1;
                su += e0 + e1;
            }
            su += __shfl_xor_sync(0xffffffffu, su, 1);
            su += __shfl_xor_sync(0xffffffffu, su, 2);
            if (tc == 0) red2[row * 8 + wid] = su;
        }
    }
    __syncthreads();
    // pass 3: normalize + write fp16 probs
    #pragma unroll
    for (int mt = 0; mt < 2; mt++) {
        #pragma unroll
        for (int half = 0; half < 2; half++) {
            int row = mt * 16 + g + half * 8;
            float tot = red2[row * 8];
            #pragma unroll
            for (int w = 1; w < 8; w++) tot += red2[row * 8 + w];
            float inv = 1.f / tot;
            size_t base = ((size_t)z * 256 + m0 + row) * 256;
            #pragma unroll
            for (int nt = 0; nt < 4; nt++) {
                __half2 hp;
                hp.x = __float2half(acc[mt][nt][half * 2] * inv);
                hp.y = __float2half(acc[mt][nt][half * 2 + 1] * inv);
                *(__half2*)&ah[base + wn + nt * 8 + tc * 2] = hp;
            }
        }
    }
}

// ---------------------------------------------------------------------------
// Merged weight transpose + fp16 convert (one launch; keeps gemm3 at idx 3).
// ---------------------------------------------------------------------------
#define NT1 ((UVQK / 32) * (HD / 32))
#define NT2 ((HD / 32) * (ED / 32))
#define WCONV_GRID (NLAYERS * (NT1 + NT2))

__global__ void wconv_kernel(const float* __restrict__ Wuv,
                             const float* __restrict__ Wout,
                             __half* __restrict__ wuvh,
                             __half* __restrict__ woh) {
    int idx = blockIdx.x;
    int layer = idx / (NT1 + NT2);
    int r = idx % (NT1 + NT2);
    const float* in; __half* oh; int K, N, nb, kb;
    if (r < NT1) {
        K = HD; N = UVQK; nb = r % (UVQK / 32); kb = r / (UVQK / 32);
        in = Wuv + (size_t)layer * HD * UVQK;
        oh = wuvh + (size_t)layer * HD * UVQK;
    } else {
        r -= NT1;
        K = ED; N = HD; nb = r % (HD / 32); kb = r / (HD / 32);
        in = Wout + (size_t)layer * ED * HD;
        oh = woh + (size_t)layer * ED * HD;
    }
    __shared__ float tile[32][33];
    int n0 = nb * 32, k0 = kb * 32;
    int tx = threadIdx.x & 31, ty = threadIdx.x >> 5;
    #pragma unroll
    for (int i = 0; i < 4; i++)
        tile[ty + i * 8][tx] = in[(size_t)(k0 + ty + i * 8) * N + n0 + tx];
    __syncthreads();
    #pragma unroll
    for (int i = 0; i < 4; i++) {
        int n = n0 + ty + i * 8, k = k0 + tx;
        oh[(size_t)n * K + k] = __float2half(tile[tx][ty + i * 8]);
    }
}

// ---------------------------------------------------------------------------
// Patchify + patch_W GEMM + time-embedding bias (validated round 1).
// ---------------------------------------------------------------------------
__global__ void patch_kernel(const float* __restrict__ x,
                             const int*   __restrict__ t_idx,
                             const float* __restrict__ pw,
                             const float* __restrict__ temb) {
    int r = blockIdx.x;
    int b = r >> 8, l = r & 255;
    int gy = l >> 4, gx = l & 15;
    int t = threadIdx.x;
    __shared__ float xr[PDIM];
    if (t < PDIM) {
        int py = t / 24, rem = t % 24, px = rem / 3, c = rem % 3;
        xr[t] = x[(((size_t)(b * 3 + c) * 128) + (gy * 8 + py)) * 128 + gx * 8 + px];
    }
    __syncthreads();
    const float* bias = temb + (size_t)t_idx[b] * HD;
    for (int col = t; col < HD; col += 256) {
        float s = 0.f;
        #pragma unroll 4
        for (int k = 0; k < PDIM; k++) s += xr[k] * pw[(size_t)k * HD + col];
        g_h[(size_t)r * HD + col] = s + bias[col];
    }
}

// ---------------------------------------------------------------------------
// RMSNorm: fp16 out always; fp32 out only when outp != nullptr.
// ---------------------------------------------------------------------------
__global__ void rmsnorm_kernel(const float* __restrict__ in,
                               const float* __restrict__ w,
                               float* __restrict__ outp,
                               __half* __restrict__ oh) {
    int r = blockIdx.x, t = threadIdx.x;
    int lane = t & 31, wid = t >> 5;
    const float* row = in + (size_t)r * HD;
    float v0 = row[t], v1 = row[t + 256], v2 = row[t + 512];
    float ss = v0 * v0 + v1 * v1 + v2 * v2;
    #pragma unroll
    for (int o = 16; o > 0; o >>= 1) ss += __shfl_xor_sync(0xffffffffu, ss, o);
    __shared__ float wred[8];
    if (lane == 0) wred[wid] = ss;
    __syncthreads();
    float tot = wred[0];
    #pragma unroll
    for (int i = 1; i < 8; i++) tot += wred[i];
    float inv = 1.f / (sqrtf(tot * (1.0f / HD)) + 1e-6f);
    size_t base = (size_t)r * HD;
    #pragma unroll
    for (int i = 0; i < 3; i++) {
        int c = t + i * 256;
        float v = (i == 0 ? v0 : i == 1 ? v1 : v2) * inv * w[c];
        if (outp) outp[base + c] = v;
        oh[base + c] = __float2half(v);
    }
}

// ---------------------------------------------------------------------------
// Final unpatch (validated round 1).
// ---------------------------------------------------------------------------
__global__ void unpatch_kernel(const float* __restrict__ uw, float* __restrict__ out) {
    int r = blockIdx.x, t = threadIdx.x;
    int b = r >> 8, l = r & 255, gy = l >> 4, gx = l & 15;
    __shared__ float xr[HD];
    const float* row = g_xn + (size_t)r * HD;
    xr[t] = row[t]; xr[t + 256] = row[t + 256]; xr[t + 512] = row[t + 512];
    __syncthreads();
    if (t < PDIM) {
        float s = 0.f;
        #pragma unroll 4
        for (int k = 0; k < HD; k++) s += xr[k] * uw[(size_t)k * PDIM + t];
        int py = t / 24, rem = t % 24, px = rem / 3, c = rem % 3;
        out[(((size_t)(b * 3 + c) * 128) + (gy * 8 + py)) * 128 + gx * 8 + px] = s;
    }
}

// ---------------------------------------------------------------------------
// Host launcher
// ---------------------------------------------------------------------------
extern "C" void kernel_launch(void* const* d_in, const int* in_sizes, int n_in,
                              void* d_out, int out_size) {
    const float* x        = (const float*)d_in[0];
    const int*   t_idx    = (const int*)  d_in[1];
    const float* patch_W  = (const float*)d_in[2];
    const float* t_emb    = (const float*)d_in[3];
    const float* Wuv      = (const float*)d_in[4];
    const float* Wout     = (const float*)d_in[5];
    const float* gnorm    = (const float*)d_in[6];
    const float* fnorm_w  = (const float*)d_in[7];
    const float* unpatchW = (const float*)d_in[8];
    float* out = (float*)d_out;

    float *h, *xn;
    __half *xnh, *uh, *qh, *kh, *ath, *vth, *oh, *wuvh, *woh;
    cudaGetSymbolAddress((void**)&h,     g_h);
    cudaGetSymbolAddress((void**)&xn,    g_xn);
    cudaGetSymbolAddress((void**)&xnh,   g_xnh);
    cudaGetSymbolAddress((void**)&uh,    g_uh);
    cudaGetSymbolAddress((void**)&qh,    g_qh);
    cudaGetSymbolAddress((void**)&kh,    g_kh);
    cudaGetSymbolAddress((void**)&ath,   g_attnh);
    cudaGetSymbolAddress((void**)&vth,   g_vth);
    cudaGetSymbolAddress((void**)&oh,    g_oh);
    cudaGetSymbolAddress((void**)&wuvh,  g_wuvh);
    cudaGetSymbolAddress((void**)&woh,   g_woh);

    cudaFuncSetAttribute(mma_gemm<1>, cudaFuncAttributeMaxDynamicSharedMemorySize, GSMEM_SZ);
    cudaFuncSetAttribute(mma_gemm<2>, cudaFuncAttributeMaxDynamicSharedMemorySize, GSMEM_SZ);
    cudaFuncSetAttribute(mma_gemm<3>, cudaFuncAttributeMaxDynamicSharedMemorySize, GSMEM_SZ);
    cudaFuncSetAttribute(attn_fused,  cudaFuncAttributeMaxDynamicSharedMemorySize, AT_SMEM);

    // launch 0: merged weight transpose + fp16 convert
    wconv_kernel<<<WCONV_GRID, 256>>>(Wuv, Wout, wuvh, woh);

    // launch 1
    patch_kernel<<<ROWS, 256>>>(x, t_idx, patch_W, t_emb);

    for (int l = 0; l < NLAYERS; l++) {
        // launch 2 (first iter)
        rmsnorm_kernel<<<ROWS, 256>>>(h, gnorm + (size_t)l * HD, nullptr, xnh);

        // launch 3 (first iter) -> ncu-captured: fused uvqk GEMM + epilogues
        mma_gemm<3><<<dim3(UVQK / 128, ROWS / 128, 1), 256, GSMEM_SZ>>>(
            xnh, wuvh + (size_t)l * UVQK * HD,
            nullptr, nullptr, uh, vth, qh, kh,
            HD, HD, HD, 0, 0, 0,
            0, 0, 0, 0, 0);

        // fused scores + softmax
        attn_fused<<<dim3(8, NB), 256, AT_SMEM>>>(qh, kh, ath);

        // o = uh * (attn @ v)   per batch (256 x 1536 x 256)
        mma_gemm<1><<<dim3(ED / 128, LTOK / 128, NB), 256, GSMEM_SZ>>>(
            ath, vth, nullptr, uh, oh, nullptr, nullptr, nullptr,
            LTOK, LTOK, LTOK, 0, ED, ED,
            (long)LTOK * LTOK, (long)ED * LTOK, 0,
            (long)LTOK * ED, (long)LTOK * ED);

        // h += o @ Wout[l]   (4096 x 768 x 1536), fused residual
        mma_gemm<2><<<dim3(HD / 128, ROWS / 128, 1), 256, GSMEM_SZ>>>(
            oh, woh + (size_t)l * HD * ED,
            h, nullptr, nullptr, nullptr, nullptr, nullptr,
            ED, ED, ED, HD, 0, 0,
            0, 0, 0, 0, 0);
    }

    rmsnorm_kernel<<<ROWS, 256>>>(h, fnorm_w, xn, xnh);
    unpatch_kernel<<<ROWS, 256>>>(unpatchW, out);
}